// round 1
// baseline (speedup 1.0000x reference)
#include <cuda_runtime.h>
#include <math.h>

// ---------------- problem constants ----------------
#define BATCH 2
#define CC    128           // channels
#define HH    128
#define WW    128
#define HWSZ  16384         // 128*128
#define HS    64            // feat_s spatial
#define DGRP  8             // deformable groups
#define CG    16            // channels per group
#define KPTS  9             // 3x3
#define OMCH  216           // DG*3*KK
#define KBIG  1152          // CC*9 == DG*CG*9

// ---------------- scratch (device globals: allocation-free) ----------------
__device__ float g_pooled[BATCH * CC];
__device__ float g_scale [BATCH * CC];                       // 1 + sigmoid(bn(fc(pool)))
__device__ float g_armW  [BATCH * CC * CC];                  // fsm_w * scale (per-batch A matrix)
__device__ float g_cat   [(size_t)BATCH * 2 * CC * HWSZ];    // rows 0..127 feat_arm, 128..255 feat_up
__device__ float g_off   [(size_t)BATCH * CC * HWSZ];        // offset feature (1x1 conv out)
__device__ float g_col   [(size_t)BATCH * KBIG * HWSZ];      // im2col of g_off
__device__ float g_om    [(size_t)BATCH * OMCH * HWSZ];      // offset/mask conv out
__device__ float g_S     [(size_t)BATCH * KBIG * HWSZ];      // sampled+masked DCN input

// ---------------- small kernels ----------------
__global__ void pool_kernel(const float* __restrict__ x) {
    int bc = blockIdx.x;                       // b*C + c
    const float4* p = (const float4*)(x + (size_t)bc * HWSZ);
    float s = 0.f;
    for (int i = threadIdx.x; i < HWSZ / 4; i += 256) {
        float4 v = p[i];
        s += v.x + v.y + v.z + v.w;
    }
    __shared__ float sh[256];
    sh[threadIdx.x] = s;
    __syncthreads();
    for (int o = 128; o > 0; o >>= 1) {
        if (threadIdx.x < o) sh[threadIdx.x] += sh[threadIdx.x + o];
        __syncthreads();
    }
    if (threadIdx.x == 0) g_pooled[bc] = sh[0] * (1.0f / HWSZ);
}

__global__ void atten_kernel(const float* __restrict__ aw, const float* __restrict__ ab,
                             const float* __restrict__ bg, const float* __restrict__ bb,
                             const float* __restrict__ bm, const float* __restrict__ bv) {
    int t = threadIdx.x;            // 256 = B*C
    int b = t >> 7, o = t & 127;
    float a = ab[o];
    const float* pr = g_pooled + b * CC;
    const float* wr = aw + o * CC;
    #pragma unroll 4
    for (int c = 0; c < CC; c++) a += pr[c] * wr[c];
    a = (a - bm[o]) * rsqrtf(bv[o] + 1e-5f) * bg[o] + bb[o];
    g_scale[t] = 1.f + 1.f / (1.f + expf(-a));
}

__global__ void armw_kernel(const float* __restrict__ fsm_w) {
    int i = blockIdx.x * blockDim.x + threadIdx.x;   // B*C*C = 32768
    int c = i & 127;
    int bo = i >> 7;
    int o = bo & 127;
    int b = bo >> 7;
    g_armW[i] = fsm_w[o * CC + c] * g_scale[b * CC + c];
}

__global__ void upsample_kernel(const float* __restrict__ fs) {
    int i = blockIdx.x * blockDim.x + threadIdx.x;
    if (i >= BATCH * CC * HWSZ) return;
    int n = i & (HWSZ - 1);
    int bc = i >> 14;
    int b = bc >> 7, c = bc & 127;
    int h = n >> 7, w = n & 127;
    float fy = (h * 63.0f) / 127.0f;
    float fx = (w * 63.0f) / 127.0f;
    int y0 = (int)floorf(fy); float wy = fy - y0; int y1 = min(y0 + 1, 63);
    int x0 = (int)floorf(fx); float wx = fx - x0; int x1 = min(x0 + 1, 63);
    const float* p = fs + (size_t)bc * (HS * HS);
    float v = p[y0 * HS + x0] * (1.f - wy) * (1.f - wx)
            + p[y0 * HS + x1] * (1.f - wy) * wx
            + p[y1 * HS + x0] * wy * (1.f - wx)
            + p[y1 * HS + x1] * wy * wx;
    g_cat[((size_t)b * 2 * CC + CC + c) * HWSZ + n] = v;
}

__global__ void im2col_kernel() {
    size_t i = (size_t)blockIdx.x * blockDim.x + threadIdx.x;
    if (i >= (size_t)BATCH * KBIG * HWSZ) return;
    int n  = (int)(i & (HWSZ - 1));
    size_t t = i >> 14;
    int ck = (int)(t % KBIG);
    int b  = (int)(t / KBIG);
    int c = ck / 9, k = ck % 9;
    int h = (n >> 7) + (k / 3) - 1;
    int w = (n & 127) + (k % 3) - 1;
    float v = 0.f;
    if ((unsigned)h < 128u && (unsigned)w < 128u)
        v = g_off[((size_t)b * CC + c) * HWSZ + (h << 7) + w];
    g_col[i] = v;
}

__global__ void sample_kernel() {
    int i = blockIdx.x * blockDim.x + threadIdx.x;
    if (i >= BATCH * DGRP * KPTS * HWSZ) return;
    int n = i & (HWSZ - 1);
    int t = i >> 14;
    int k = t % KPTS; t /= KPTS;
    int g = t & 7;
    int b = t >> 3;
    int h = n >> 7, w = n & 127;

    const float* om = g_om + (size_t)b * OMCH * HWSZ;
    int gk = g * KPTS + k;
    float offy = om[(size_t)gk * HWSZ + n];
    float offx = om[(size_t)(72 + gk) * HWSZ + n];
    float mm   = om[(size_t)(144 + gk) * HWSZ + n];
    mm = 1.f / (1.f + expf(-mm));

    float py = (float)(h + k / 3 - 1) + offy;
    float px = (float)(w + k % 3 - 1) + offx;
    float y0f = floorf(py), x0f = floorf(px);
    float ly = py - y0f, lx = px - x0f;
    int y0 = (int)y0f, x0 = (int)x0f;
    int y1 = y0 + 1, x1 = x0 + 1;
    bool vy0 = (y0 >= 0 && y0 < 128), vy1 = (y1 >= 0 && y1 < 128);
    bool vx0 = (x0 >= 0 && x0 < 128), vx1 = (x1 >= 0 && x1 < 128);
    int cy0 = min(max(y0, 0), 127), cy1 = min(max(y1, 0), 127);
    int cx0 = min(max(x0, 0), 127), cx1 = min(max(x1, 0), 127);
    float w00 = (vy0 && vx0) ? (1.f - ly) * (1.f - lx) * mm : 0.f;
    float w01 = (vy0 && vx1) ? (1.f - ly) * lx * mm : 0.f;
    float w10 = (vy1 && vx0) ? ly * (1.f - lx) * mm : 0.f;
    float w11 = (vy1 && vx1) ? ly * lx * mm : 0.f;
    int i00 = (cy0 << 7) + cx0, i01 = (cy0 << 7) + cx1;
    int i10 = (cy1 << 7) + cx0, i11 = (cy1 << 7) + cx1;

    const float* fu = g_cat + ((size_t)b * 2 * CC + CC + g * CG) * HWSZ;
    float* sp = g_S + ((size_t)b * KBIG + (size_t)g * CG * KPTS + k) * HWSZ + n;
    #pragma unroll
    for (int c = 0; c < CG; c++) {
        const float* p = fu + (size_t)c * HWSZ;
        float v = w00 * p[i00] + w01 * p[i01] + w10 * p[i10] + w11 * p[i11];
        sp[(size_t)c * KPTS * HWSZ] = v;
    }
}

// ---------------- SIMT SGEMM: C[M,N] = A[M,K] * B[K,N] (+bias) (epilogues) ----------------
// BM=BN=128, BK=8, 256 threads, 8x8 per thread.
// EPI 0: C = acc + bias
// EPI 2: C = relu(acc + bias) + Add
template<int EPI>
__global__ __launch_bounds__(256, 2) void sgemm_kernel(
    const float* __restrict__ A, int lda, size_t sA,
    const float* __restrict__ B, size_t sB,
    const float* __restrict__ bias,
    float* __restrict__ C, size_t sC,
    const float* __restrict__ Add, size_t sAdd,
    int M, int K, int N)
{
    A += (size_t)blockIdx.z * sA;
    B += (size_t)blockIdx.z * sB;
    C += (size_t)blockIdx.z * sC;
    const float* Ad = (EPI == 2) ? (Add + (size_t)blockIdx.z * sAdd) : nullptr;

    int bm = blockIdx.y * 128, bn = blockIdx.x * 128;
    __shared__ float As[8][128];
    __shared__ float Bs[8][128];
    int tid = threadIdx.x;
    int arow = tid >> 1, acol = (tid & 1) << 2;
    int brow = tid >> 5, bcol = (tid & 31) << 2;
    int ty = tid >> 4, tx = tid & 15;

    float acc[8][8];
    #pragma unroll
    for (int i = 0; i < 8; i++)
        #pragma unroll
        for (int j = 0; j < 8; j++) acc[i][j] = 0.f;

    const float* Ap = A + (size_t)(bm + arow) * lda + acol;
    const float* Bp = B + (size_t)brow * N + bn + bcol;
    bool aok = (bm + arow) < M;
    int nk = K >> 3;

    for (int kb = 0; kb < nk; kb++) {
        float4 av = aok ? *(const float4*)Ap : make_float4(0.f, 0.f, 0.f, 0.f);
        float4 bv = *(const float4*)Bp;
        As[acol + 0][arow] = av.x;
        As[acol + 1][arow] = av.y;
        As[acol + 2][arow] = av.z;
        As[acol + 3][arow] = av.w;
        *(float4*)(&Bs[brow][bcol]) = bv;
        __syncthreads();
        #pragma unroll
        for (int kk = 0; kk < 8; kk++) {
            float ra[8], rb[8];
            *(float4*)(ra)     = *(const float4*)(&As[kk][ty * 8]);
            *(float4*)(ra + 4) = *(const float4*)(&As[kk][ty * 8 + 4]);
            *(float4*)(rb)     = *(const float4*)(&Bs[kk][tx * 8]);
            *(float4*)(rb + 4) = *(const float4*)(&Bs[kk][tx * 8 + 4]);
            #pragma unroll
            for (int i = 0; i < 8; i++)
                #pragma unroll
                for (int j = 0; j < 8; j++)
                    acc[i][j] += ra[i] * rb[j];
        }
        __syncthreads();
        Ap += 8;
        Bp += (size_t)8 * N;
    }

    #pragma unroll
    for (int i = 0; i < 8; i++) {
        int r = bm + ty * 8 + i;
        if (r >= M) continue;
        float bvv = bias ? bias[r] : 0.f;
        size_t rowoff = (size_t)r * N + bn + tx * 8;
        #pragma unroll
        for (int j = 0; j < 8; j++) {
            float v = acc[i][j] + bvv;
            if (EPI == 2) v = fmaxf(v, 0.f) + Ad[rowoff + j];
            C[rowoff + j] = v;
        }
    }
}

// ---------------- launch ----------------
extern "C" void kernel_launch(void* const* d_in, const int* in_sizes, int n_in,
                              void* d_out, int out_size) {
    const float* feat_l  = (const float*)d_in[0];
    const float* feat_s  = (const float*)d_in[1];
    const float* atten_w = (const float*)d_in[2];
    const float* atten_b = (const float*)d_in[3];
    const float* bn_g    = (const float*)d_in[4];
    const float* bn_b    = (const float*)d_in[5];
    const float* bn_m    = (const float*)d_in[6];
    const float* bn_v    = (const float*)d_in[7];
    const float* fsm_w   = (const float*)d_in[8];
    const float* fsm_b   = (const float*)d_in[9];
    const float* off_w   = (const float*)d_in[10];
    const float* om_w    = (const float*)d_in[11];
    const float* om_b    = (const float*)d_in[12];
    const float* dcn_w   = (const float*)d_in[13];
    const float* dcn_b   = (const float*)d_in[14];
    float* out = (float*)d_out;

    float *p_armW, *p_cat, *p_off, *p_col, *p_om, *p_S;
    cudaGetSymbolAddress((void**)&p_armW, g_armW);
    cudaGetSymbolAddress((void**)&p_cat,  g_cat);
    cudaGetSymbolAddress((void**)&p_off,  g_off);
    cudaGetSymbolAddress((void**)&p_col,  g_col);
    cudaGetSymbolAddress((void**)&p_om,   g_om);
    cudaGetSymbolAddress((void**)&p_S,    g_S);

    // 1) SE gate
    pool_kernel<<<BATCH * CC, 256>>>(feat_l);
    atten_kernel<<<1, 256>>>(atten_w, atten_b, bn_g, bn_b, bn_m, bn_v);
    armw_kernel<<<128, 256>>>(fsm_w);

    // 2) upsample feat_s into cat rows 128..255
    upsample_kernel<<<(BATCH * CC * HWSZ + 255) / 256, 256>>>(feat_s);

    // 3) feat_arm = (fsm_w*scale) @ feat_l + fsm_b  -> cat rows 0..127
    sgemm_kernel<0><<<dim3(HWSZ / 128, 1, BATCH), 256>>>(
        p_armW, CC, (size_t)CC * CC,
        feat_l, (size_t)CC * HWSZ,
        fsm_b,
        p_cat, (size_t)2 * CC * HWSZ,
        nullptr, 0,
        CC, CC, HWSZ);

    // 4) off_feat = off_w @ [feat_arm; feat_up]   (K = 256, no bias)
    sgemm_kernel<0><<<dim3(HWSZ / 128, 1, BATCH), 256>>>(
        off_w, 2 * CC, 0,
        p_cat, (size_t)2 * CC * HWSZ,
        nullptr,
        p_off, (size_t)CC * HWSZ,
        nullptr, 0,
        CC, 2 * CC, HWSZ);

    // 5) im2col of off_feat, then 3x3 conv as GEMM (M=216, K=1152)
    im2col_kernel<<<(int)(((size_t)BATCH * KBIG * HWSZ + 255) / 256), 256>>>();
    sgemm_kernel<0><<<dim3(HWSZ / 128, 2, BATCH), 256>>>(
        om_w, KBIG, 0,
        p_col, (size_t)KBIG * HWSZ,
        om_b,
        p_om, (size_t)OMCH * HWSZ,
        nullptr, 0,
        OMCH, KBIG, HWSZ);

    // 6) bilinear sample + mask -> S
    sample_kernel<<<(BATCH * DGRP * KPTS * HWSZ + 255) / 256, 256>>>();

    // 7) DCN einsum as GEMM + relu + bias + feat_arm  -> out
    sgemm_kernel<2><<<dim3(HWSZ / 128, 1, BATCH), 256>>>(
        dcn_w, KBIG, 0,
        p_S, (size_t)KBIG * HWSZ,
        dcn_b,
        out, (size_t)CC * HWSZ,
        p_cat, (size_t)2 * CC * HWSZ,
        CC, KBIG, HWSZ);
}

// round 3
// speedup vs baseline: 2.0274x; 2.0274x over previous
#include <cuda_runtime.h>
#include <cstdint>
#include <stdint.h>
#include <math.h>

// ---------------- problem constants ----------------
#define BATCH 2
#define CC    128           // channels
#define HH    128
#define WW    128
#define HWSZ  16384         // 128*128
#define HS    64            // feat_s spatial
#define DGRP  8             // deformable groups
#define CG    16            // channels per group
#define KPTS  9             // 3x3
#define OMCH  216           // DG*3*KK
#define KBIG  1152          // CC*9 == DG*CG*9

// ---------------- scratch (device globals: allocation-free) ----------------
__device__ float g_pooled[BATCH * CC];
__device__ float g_scale [BATCH * CC];
__device__ float g_armW  [BATCH * CC * CC];
__device__ float g_cat   [(size_t)BATCH * 2 * CC * HWSZ];    // rows 0..127 feat_arm, 128..255 feat_up
__device__ float g_off   [(size_t)BATCH * CC * HWSZ];
__device__ float g_col   [(size_t)BATCH * KBIG * HWSZ];
__device__ float g_om    [(size_t)BATCH * OMCH * HWSZ];
__device__ float g_S     [(size_t)BATCH * KBIG * HWSZ];

// ---------------- small kernels ----------------
__global__ void pool_kernel(const float* __restrict__ x) {
    int bc = blockIdx.x;
    const float4* p = (const float4*)(x + (size_t)bc * HWSZ);
    float s = 0.f;
    for (int i = threadIdx.x; i < HWSZ / 4; i += 256) {
        float4 v = p[i];
        s += v.x + v.y + v.z + v.w;
    }
    __shared__ float sh[256];
    sh[threadIdx.x] = s;
    __syncthreads();
    for (int o = 128; o > 0; o >>= 1) {
        if (threadIdx.x < o) sh[threadIdx.x] += sh[threadIdx.x + o];
        __syncthreads();
    }
    if (threadIdx.x == 0) g_pooled[bc] = sh[0] * (1.0f / HWSZ);
}

__global__ void atten_kernel(const float* __restrict__ aw, const float* __restrict__ ab,
                             const float* __restrict__ bg, const float* __restrict__ bb,
                             const float* __restrict__ bm, const float* __restrict__ bv) {
    int t = threadIdx.x;
    int b = t >> 7, o = t & 127;
    float a = ab[o];
    const float* pr = g_pooled + b * CC;
    const float* wr = aw + o * CC;
    #pragma unroll 4
    for (int c = 0; c < CC; c++) a += pr[c] * wr[c];
    a = (a - bm[o]) * rsqrtf(bv[o] + 1e-5f) * bg[o] + bb[o];
    g_scale[t] = 1.f + 1.f / (1.f + expf(-a));
}

__global__ void armw_kernel(const float* __restrict__ fsm_w) {
    int i = blockIdx.x * blockDim.x + threadIdx.x;
    int c = i & 127;
    int bo = i >> 7;
    int o = bo & 127;
    int b = bo >> 7;
    g_armW[i] = fsm_w[o * CC + c] * g_scale[b * CC + c];
}

__global__ void upsample_kernel(const float* __restrict__ fs) {
    int i = blockIdx.x * blockDim.x + threadIdx.x;
    if (i >= BATCH * CC * HWSZ) return;
    int n = i & (HWSZ - 1);
    int bc = i >> 14;
    int b = bc >> 7, c = bc & 127;
    int h = n >> 7, w = n & 127;
    float fy = (h * 63.0f) / 127.0f;
    float fx = (w * 63.0f) / 127.0f;
    int y0 = (int)floorf(fy); float wy = fy - y0; int y1 = min(y0 + 1, 63);
    int x0 = (int)floorf(fx); float wx = fx - x0; int x1 = min(x0 + 1, 63);
    const float* p = fs + (size_t)bc * (HS * HS);
    float v = p[y0 * HS + x0] * (1.f - wy) * (1.f - wx)
            + p[y0 * HS + x1] * (1.f - wy) * wx
            + p[y1 * HS + x0] * wy * (1.f - wx)
            + p[y1 * HS + x1] * wy * wx;
    g_cat[((size_t)b * 2 * CC + CC + c) * HWSZ + n] = v;
}

__global__ void im2col_kernel() {
    size_t i = (size_t)blockIdx.x * blockDim.x + threadIdx.x;
    if (i >= (size_t)BATCH * KBIG * HWSZ) return;
    int n  = (int)(i & (HWSZ - 1));
    size_t t = i >> 14;
    int ck = (int)(t % KBIG);
    int b  = (int)(t / KBIG);
    int c = ck / 9, k = ck % 9;
    int h = (n >> 7) + (k / 3) - 1;
    int w = (n & 127) + (k % 3) - 1;
    float v = 0.f;
    if ((unsigned)h < 128u && (unsigned)w < 128u)
        v = g_off[((size_t)b * CC + c) * HWSZ + (h << 7) + w];
    g_col[i] = v;
}

__global__ void sample_kernel() {
    int i = blockIdx.x * blockDim.x + threadIdx.x;
    if (i >= BATCH * DGRP * KPTS * HWSZ) return;
    int n = i & (HWSZ - 1);
    int t = i >> 14;
    int k = t % KPTS; t /= KPTS;
    int g = t & 7;
    int b = t >> 3;
    int h = n >> 7, w = n & 127;

    const float* om = g_om + (size_t)b * OMCH * HWSZ;
    int gk = g * KPTS + k;
    float offy = om[(size_t)gk * HWSZ + n];
    float offx = om[(size_t)(72 + gk) * HWSZ + n];
    float mm   = om[(size_t)(144 + gk) * HWSZ + n];
    mm = 1.f / (1.f + expf(-mm));

    float py = (float)(h + k / 3 - 1) + offy;
    float px = (float)(w + k % 3 - 1) + offx;
    float y0f = floorf(py), x0f = floorf(px);
    float ly = py - y0f, lx = px - x0f;
    int y0 = (int)y0f, x0 = (int)x0f;
    int y1 = y0 + 1, x1 = x0 + 1;
    bool vy0 = (y0 >= 0 && y0 < 128), vy1 = (y1 >= 0 && y1 < 128);
    bool vx0 = (x0 >= 0 && x0 < 128), vx1 = (x1 >= 0 && x1 < 128);
    int cy0 = min(max(y0, 0), 127), cy1 = min(max(y1, 0), 127);
    int cx0 = min(max(x0, 0), 127), cx1 = min(max(x1, 0), 127);
    float w00 = (vy0 && vx0) ? (1.f - ly) * (1.f - lx) * mm : 0.f;
    float w01 = (vy0 && vx1) ? (1.f - ly) * lx * mm : 0.f;
    float w10 = (vy1 && vx0) ? ly * (1.f - lx) * mm : 0.f;
    float w11 = (vy1 && vx1) ? ly * lx * mm : 0.f;
    int i00 = (cy0 << 7) + cx0, i01 = (cy0 << 7) + cx1;
    int i10 = (cy1 << 7) + cx0, i11 = (cy1 << 7) + cx1;

    const float* fu = g_cat + ((size_t)b * 2 * CC + CC + g * CG) * HWSZ;
    float* sp = g_S + ((size_t)b * KBIG + (size_t)g * CG * KPTS + k) * HWSZ + n;
    #pragma unroll
    for (int c = 0; c < CG; c++) {
        const float* p = fu + (size_t)c * HWSZ;
        float v = w00 * p[i00] + w01 * p[i01] + w10 * p[i10] + w11 * p[i11];
        sp[(size_t)c * KPTS * HWSZ] = v;
    }
}

// ---------------- TF32 tensor-core GEMM ----------------
// C[M,N] = A[M,K] @ B[K,N] (+bias) with epilogues.
// BM=BN=128, BK=16, 256 threads (8 warps, 2x4 grid, 64x32 warp tile),
// mma.sync.m16n8k8 tf32, cp.async double-buffered.
// EPI 0: C = acc + bias ; EPI 2: C = relu(acc + bias) + Add
#define ASTR 20   // padded A smem stride (floats); 80B rows keep 16B alignment

template<int EPI>
__global__ __launch_bounds__(256, 2) void mma_gemm(
    const float* __restrict__ A, int lda, size_t sA,
    const float* __restrict__ B, size_t sB,
    const float* __restrict__ bias,
    float* __restrict__ C, size_t sC,
    const float* __restrict__ Add, size_t sAdd,
    int M, int K, int N)
{
    A += (size_t)blockIdx.z * sA;
    B += (size_t)blockIdx.z * sB;
    C += (size_t)blockIdx.z * sC;
    const float* Ad = (EPI == 2) ? (Add + (size_t)blockIdx.z * sAdd) : nullptr;

    __shared__ __align__(16) float As[2][128 * ASTR];   // [m][k]
    __shared__ __align__(16) float Bs[2][16 * 128];     // [k][n]

    const int tid = threadIdx.x, lane = tid & 31, warp = tid >> 5;
    const int gid = lane >> 2, tig = lane & 3;
    const int wm = (warp >> 2) * 64, wn = (warp & 3) * 32;
    const int bm = blockIdx.y * 128, bn = blockIdx.x * 128;

    const int arow = tid >> 1, acol = (tid & 1) * 8;    // A: 128 rows x 16 k
    const int brow = tid >> 4, bcol = (tid & 15) * 8;   // B: 16 k x 128 n

    const float* Ap = A + (size_t)(bm + arow) * lda + acol;
    const float* Bp = B + (size_t)brow * N + bn + bcol;
    const int apred = ((bm + arow) < M) ? 16 : 0;

    float acc[4][4][4];
    #pragma unroll
    for (int mi = 0; mi < 4; mi++)
        #pragma unroll
        for (int ni = 0; ni < 4; ni++)
            #pragma unroll
            for (int r = 0; r < 4; r++) acc[mi][ni][r] = 0.f;

    const int nk = K >> 4;

    // prologue: stage 0
    {
        unsigned int sa = (unsigned int)__cvta_generic_to_shared(&As[0][arow * ASTR + acol]);
        asm volatile("cp.async.ca.shared.global [%0], [%1], 16, %2;\n" :: "r"(sa), "l"(Ap), "r"(apred));
        asm volatile("cp.async.ca.shared.global [%0], [%1], 16, %2;\n" :: "r"(sa + 16), "l"(Ap + 4), "r"(apred));
        unsigned int sb = (unsigned int)__cvta_generic_to_shared(&Bs[0][brow * 128 + bcol]);
        asm volatile("cp.async.ca.shared.global [%0], [%1], 16;\n" :: "r"(sb), "l"(Bp));
        asm volatile("cp.async.ca.shared.global [%0], [%1], 16;\n" :: "r"(sb + 16), "l"(Bp + 4));
        asm volatile("cp.async.commit_group;\n");
    }

    for (int kb = 0; kb < nk; kb++) {
        const int cur = kb & 1;
        if (kb + 1 < nk) {
            const int nxt = cur ^ 1;
            const float* ga = Ap + (kb + 1) * 16;
            unsigned int sa = (unsigned int)__cvta_generic_to_shared(&As[nxt][arow * ASTR + acol]);
            asm volatile("cp.async.ca.shared.global [%0], [%1], 16, %2;\n" :: "r"(sa), "l"(ga), "r"(apred));
            asm volatile("cp.async.ca.shared.global [%0], [%1], 16, %2;\n" :: "r"(sa + 16), "l"(ga + 4), "r"(apred));
            const float* gb = Bp + (size_t)(kb + 1) * 16 * N;
            unsigned int sb = (unsigned int)__cvta_generic_to_shared(&Bs[nxt][brow * 128 + bcol]);
            asm volatile("cp.async.ca.shared.global [%0], [%1], 16;\n" :: "r"(sb), "l"(gb));
            asm volatile("cp.async.ca.shared.global [%0], [%1], 16;\n" :: "r"(sb + 16), "l"(gb + 4));
            asm volatile("cp.async.commit_group;\n");
            asm volatile("cp.async.wait_group 1;\n");
        } else {
            asm volatile("cp.async.wait_group 0;\n");
        }
        __syncthreads();

        #pragma unroll
        for (int ks = 0; ks < 2; ks++) {
            const int k0 = ks * 8;
            unsigned int af[4][4];
            unsigned int bf[4][2];
            #pragma unroll
            for (int mi = 0; mi < 4; mi++) {
                const float* ab = &As[cur][(wm + mi * 16 + gid) * ASTR + k0 + tig];
                float a0 = ab[0];
                float a2 = ab[4];
                float a1 = ab[8 * ASTR];
                float a3 = ab[8 * ASTR + 4];
                asm("cvt.rna.tf32.f32 %0, %1;" : "=r"(af[mi][0]) : "f"(a0));
                asm("cvt.rna.tf32.f32 %0, %1;" : "=r"(af[mi][1]) : "f"(a1));
                asm("cvt.rna.tf32.f32 %0, %1;" : "=r"(af[mi][2]) : "f"(a2));
                asm("cvt.rna.tf32.f32 %0, %1;" : "=r"(af[mi][3]) : "f"(a3));
            }
            #pragma unroll
            for (int ni = 0; ni < 4; ni++) {
                const float* bb = &Bs[cur][(k0 + tig) * 128 + wn + ni * 8 + gid];
                float b0 = bb[0];
                float b1 = bb[4 * 128];
                asm("cvt.rna.tf32.f32 %0, %1;" : "=r"(bf[ni][0]) : "f"(b0));
                asm("cvt.rna.tf32.f32 %0, %1;" : "=r"(bf[ni][1]) : "f"(b1));
            }
            #pragma unroll
            for (int mi = 0; mi < 4; mi++)
                #pragma unroll
                for (int ni = 0; ni < 4; ni++) {
                    asm volatile(
                        "mma.sync.aligned.m16n8k8.row.col.f32.tf32.tf32.f32 "
                        "{%0,%1,%2,%3}, {%4,%5,%6,%7}, {%8,%9}, {%0,%1,%2,%3};\n"
                        : "+f"(acc[mi][ni][0]), "+f"(acc[mi][ni][1]),
                          "+f"(acc[mi][ni][2]), "+f"(acc[mi][ni][3])
                        : "r"(af[mi][0]), "r"(af[mi][1]), "r"(af[mi][2]), "r"(af[mi][3]),
                          "r"(bf[ni][0]), "r"(bf[ni][1]));
                }
        }
        __syncthreads();
    }

    // epilogue
    #pragma unroll
    for (int mi = 0; mi < 4; mi++) {
        const int r0 = bm + wm + mi * 16 + gid;
        const int r1 = r0 + 8;
        const bool ok0 = r0 < M, ok1 = r1 < M;
        const float bv0 = (bias && ok0) ? bias[r0] : 0.f;
        const float bv1 = (bias && ok1) ? bias[r1] : 0.f;
        #pragma unroll
        for (int ni = 0; ni < 4; ni++) {
            const int cc = bn + wn + ni * 8 + 2 * tig;
            if (ok0) {
                size_t o = (size_t)r0 * N + cc;
                float v0 = acc[mi][ni][0] + bv0;
                float v1 = acc[mi][ni][1] + bv0;
                if (EPI == 2) {
                    float2 ad = *(const float2*)&Ad[o];
                    v0 = fmaxf(v0, 0.f) + ad.x;
                    v1 = fmaxf(v1, 0.f) + ad.y;
                }
                *(float2*)&C[o] = make_float2(v0, v1);
            }
            if (ok1) {
                size_t o = (size_t)r1 * N + cc;
                float v0 = acc[mi][ni][2] + bv1;
                float v1 = acc[mi][ni][3] + bv1;
                if (EPI == 2) {
                    float2 ad = *(const float2*)&Ad[o];
                    v0 = fmaxf(v0, 0.f) + ad.x;
                    v1 = fmaxf(v1, 0.f) + ad.y;
                }
                *(float2*)&C[o] = make_float2(v0, v1);
            }
        }
    }
}

// ---------------- launch ----------------
extern "C" void kernel_launch(void* const* d_in, const int* in_sizes, int n_in,
                              void* d_out, int out_size) {
    const float* feat_l  = (const float*)d_in[0];
    const float* feat_s  = (const float*)d_in[1];
    const float* atten_w = (const float*)d_in[2];
    const float* atten_b = (const float*)d_in[3];
    const float* bn_g    = (const float*)d_in[4];
    const float* bn_b    = (const float*)d_in[5];
    const float* bn_m    = (const float*)d_in[6];
    const float* bn_v    = (const float*)d_in[7];
    const float* fsm_w   = (const float*)d_in[8];
    const float* fsm_b   = (const float*)d_in[9];
    const float* off_w   = (const float*)d_in[10];
    const float* om_w    = (const float*)d_in[11];
    const float* om_b    = (const float*)d_in[12];
    const float* dcn_w   = (const float*)d_in[13];
    const float* dcn_b   = (const float*)d_in[14];
    float* out = (float*)d_out;

    float *p_armW, *p_cat, *p_off, *p_col, *p_om, *p_S;
    cudaGetSymbolAddress((void**)&p_armW, g_armW);
    cudaGetSymbolAddress((void**)&p_cat,  g_cat);
    cudaGetSymbolAddress((void**)&p_off,  g_off);
    cudaGetSymbolAddress((void**)&p_col,  g_col);
    cudaGetSymbolAddress((void**)&p_om,   g_om);
    cudaGetSymbolAddress((void**)&p_S,    g_S);

    // 1) SE gate
    pool_kernel<<<BATCH * CC, 256>>>(feat_l);
    atten_kernel<<<1, 256>>>(atten_w, atten_b, bn_g, bn_b, bn_m, bn_v);
    armw_kernel<<<128, 256>>>(fsm_w);

    // 2) upsample feat_s into cat rows 128..255
    upsample_kernel<<<(BATCH * CC * HWSZ + 255) / 256, 256>>>(feat_s);

    // 3) feat_arm = (fsm_w*scale) @ feat_l + fsm_b  -> cat rows 0..127
    mma_gemm<0><<<dim3(HWSZ / 128, 1, BATCH), 256>>>(
        p_armW, CC, (size_t)CC * CC,
        feat_l, (size_t)CC * HWSZ,
        fsm_b,
        p_cat, (size_t)2 * CC * HWSZ,
        nullptr, 0,
        CC, CC, HWSZ);

    // 4) off_feat = off_w @ [feat_arm; feat_up]   (K = 256, no bias)
    mma_gemm<0><<<dim3(HWSZ / 128, 1, BATCH), 256>>>(
        off_w, 2 * CC, 0,
        p_cat, (size_t)2 * CC * HWSZ,
        nullptr,
        p_off, (size_t)CC * HWSZ,
        nullptr, 0,
        CC, 2 * CC, HWSZ);

    // 5) im2col of off_feat, then 3x3 conv as GEMM (M=216, K=1152)
    im2col_kernel<<<(int)(((size_t)BATCH * KBIG * HWSZ + 255) / 256), 256>>>();
    mma_gemm<0><<<dim3(HWSZ / 128, 2, BATCH), 256>>>(
        om_w, KBIG, 0,
        p_col, (size_t)KBIG * HWSZ,
        om_b,
        p_om, (size_t)OMCH * HWSZ,
        nullptr, 0,
        OMCH, KBIG, HWSZ);

    // 6) bilinear sample + mask -> S
    sample_kernel<<<(BATCH * DGRP * KPTS * HWSZ + 255) / 256, 256>>>();

    // 7) DCN einsum as GEMM + relu + bias + feat_arm  -> out
    mma_gemm<2><<<dim3(HWSZ / 128, 1, BATCH), 256>>>(
        dcn_w, KBIG, 0,
        p_S, (size_t)KBIG * HWSZ,
        dcn_b,
        out, (size_t)CC * HWSZ,
        p_cat, (size_t)2 * CC * HWSZ,
        CC, KBIG, HWSZ);
}

// round 5
// speedup vs baseline: 2.3871x; 1.1774x over previous
#include <cuda_runtime.h>
#include <cstdint>
#include <stdint.h>
#include <math.h>

// ---------------- problem constants ----------------
#define BATCH 2
#define CC    128
#define HWSZ  16384         // 128*128
#define HS    64
#define DGRP  8
#define CG    16
#define KPTS  9
#define OMCH  216           // DG*3*KK
#define KBIG  1152          // CC*9

// ---------------- scratch ----------------
__device__ float g_pooled[BATCH * CC];
__device__ float g_scale [BATCH * CC];
__device__ float g_armW  [BATCH * CC * CC];
__device__ float g_cat   [(size_t)BATCH * 2 * CC * HWSZ];   // rows 0..127 feat_arm, 128..255 feat_up
__device__ float g_off   [(size_t)BATCH * CC * HWSZ];       // tf32-rounded
__device__ float g_om    [(size_t)BATCH * OMCH * HWSZ];
__device__ float g_S     [(size_t)BATCH * KBIG * HWSZ];     // tf32-rounded
__device__ float g_omw   [OMCH * KBIG];                     // rounded weights
__device__ float g_dcnw  [CC * KBIG];
__device__ float g_offw  [CC * 2 * CC];

__device__ __forceinline__ float tf32r(float x) {
    unsigned int u;
    asm("cvt.rna.tf32.f32 %0, %1;" : "=r"(u) : "f"(x));
    return __uint_as_float(u);
}

// ---------------- small kernels ----------------
__global__ void pool_kernel(const float* __restrict__ x) {
    int bc = blockIdx.x;
    const float4* p = (const float4*)(x + (size_t)bc * HWSZ);
    float s = 0.f;
    for (int i = threadIdx.x; i < HWSZ / 4; i += 256) {
        float4 v = p[i];
        s += v.x + v.y + v.z + v.w;
    }
    __shared__ float sh[256];
    sh[threadIdx.x] = s;
    __syncthreads();
    for (int o = 128; o > 0; o >>= 1) {
        if (threadIdx.x < o) sh[threadIdx.x] += sh[threadIdx.x + o];
        __syncthreads();
    }
    if (threadIdx.x == 0) g_pooled[bc] = sh[0] * (1.0f / HWSZ);
}

__global__ void atten_kernel(const float* __restrict__ aw, const float* __restrict__ ab,
                             const float* __restrict__ bg, const float* __restrict__ bb,
                             const float* __restrict__ bm, const float* __restrict__ bv) {
    int t = threadIdx.x;
    int b = t >> 7, o = t & 127;
    float a = ab[o];
    const float* pr = g_pooled + b * CC;
    const float* wr = aw + o * CC;
    #pragma unroll 4
    for (int c = 0; c < CC; c++) a += pr[c] * wr[c];
    a = (a - bm[o]) * rsqrtf(bv[o] + 1e-5f) * bg[o] + bb[o];
    g_scale[t] = 1.f + 1.f / (1.f + expf(-a));
}

__global__ void armw_kernel(const float* __restrict__ fsm_w) {
    int i = blockIdx.x * blockDim.x + threadIdx.x;
    int c = i & 127;
    int bo = i >> 7;
    int o = bo & 127;
    int b = bo >> 7;
    g_armW[i] = tf32r(fsm_w[o * CC + c] * g_scale[b * CC + c]);
}

__global__ void roundw_kernel(const float* __restrict__ om_w,
                              const float* __restrict__ dcn_w,
                              const float* __restrict__ off_w) {
    int i = blockIdx.x * blockDim.x + threadIdx.x;
    if (i < OMCH * KBIG) g_omw[i] = tf32r(om_w[i]);
    if (i < CC * KBIG)   g_dcnw[i] = tf32r(dcn_w[i]);
    if (i < CC * 2 * CC) g_offw[i] = tf32r(off_w[i]);
}

__global__ void upsample_kernel(const float* __restrict__ fs) {
    int i = blockIdx.x * blockDim.x + threadIdx.x;
    if (i >= BATCH * CC * HWSZ) return;
    int n = i & (HWSZ - 1);
    int bc = i >> 14;
    int b = bc >> 7, c = bc & 127;
    int h = n >> 7, w = n & 127;
    float fy = (h * 63.0f) / 127.0f;
    float fx = (w * 63.0f) / 127.0f;
    int y0 = (int)floorf(fy); float wy = fy - y0; int y1 = min(y0 + 1, 63);
    int x0 = (int)floorf(fx); float wx = fx - x0; int x1 = min(x0 + 1, 63);
    const float* p = fs + (size_t)bc * (HS * HS);
    float v = p[y0 * HS + x0] * (1.f - wy) * (1.f - wx)
            + p[y0 * HS + x1] * (1.f - wy) * wx
            + p[y1 * HS + x0] * wy * (1.f - wx)
            + p[y1 * HS + x1] * wy * wx;
    g_cat[((size_t)b * 2 * CC + CC + c) * HWSZ + n] = v;
}

__global__ void sample_kernel() {
    int i = blockIdx.x * blockDim.x + threadIdx.x;
    if (i >= BATCH * DGRP * KPTS * HWSZ) return;
    int n = i & (HWSZ - 1);
    int t = i >> 14;
    int k = t % KPTS; t /= KPTS;
    int g = t & 7;
    int b = t >> 3;
    int h = n >> 7, w = n & 127;

    const float* om = g_om + (size_t)b * OMCH * HWSZ;
    int gk = g * KPTS + k;
    float offy = om[(size_t)gk * HWSZ + n];
    float offx = om[(size_t)(72 + gk) * HWSZ + n];
    float mm   = om[(size_t)(144 + gk) * HWSZ + n];
    mm = 1.f / (1.f + expf(-mm));

    float py = (float)(h + k / 3 - 1) + offy;
    float px = (float)(w + k % 3 - 1) + offx;
    float y0f = floorf(py), x0f = floorf(px);
    float ly = py - y0f, lx = px - x0f;
    int y0 = (int)y0f, x0 = (int)x0f;
    int y1 = y0 + 1, x1 = x0 + 1;
    bool vy0 = (y0 >= 0 && y0 < 128), vy1 = (y1 >= 0 && y1 < 128);
    bool vx0 = (x0 >= 0 && x0 < 128), vx1 = (x1 >= 0 && x1 < 128);
    int cy0 = min(max(y0, 0), 127), cy1 = min(max(y1, 0), 127);
    int cx0 = min(max(x0, 0), 127), cx1 = min(max(x1, 0), 127);
    float w00 = (vy0 && vx0) ? (1.f - ly) * (1.f - lx) * mm : 0.f;
    float w01 = (vy0 && vx1) ? (1.f - ly) * lx * mm : 0.f;
    float w10 = (vy1 && vx0) ? ly * (1.f - lx) * mm : 0.f;
    float w11 = (vy1 && vx1) ? ly * lx * mm : 0.f;
    int i00 = (cy0 << 7) + cx0, i01 = (cy0 << 7) + cx1;
    int i10 = (cy1 << 7) + cx0, i11 = (cy1 << 7) + cx1;

    const float* fu = g_cat + ((size_t)b * 2 * CC + CC + g * CG) * HWSZ;
    float* sp = g_S + ((size_t)b * KBIG + (size_t)g * CG * KPTS + k) * HWSZ + n;
    #pragma unroll
    for (int c = 0; c < CG; c++) {
        const float* p = fu + (size_t)c * HWSZ;
        float v = w00 * p[i00] + w01 * p[i01] + w10 * p[i10] + w11 * p[i11];
        sp[(size_t)c * KPTS * HWSZ] = tf32r(v);
    }
}

// ---------------- TF32 tensor-core GEMM ----------------
// BM=BN=128, BK=16, 256 threads, 8 warps 2x4, m16n8k8 tf32, cp.async dbuf.
// A assumed tf32-pre-rounded. CVTB: round B on frag load.
// EPI 0: C=acc+bias ; 1: C=tf32r(acc+bias) ; 2: C=relu(acc+bias)+Add
#define ASTR 20
#define BSTR 132   // padded: conflict-free tig-row frag loads; rows stay 16B-aligned

template<int EPI, int CVTB>
__global__ __launch_bounds__(256, 2) void mma_gemm(
    const float* __restrict__ A, int lda, size_t sA,
    const float* __restrict__ B, size_t sB,
    const float* __restrict__ bias,
    float* __restrict__ C, size_t sC,
    const float* __restrict__ Add, size_t sAdd,
    int M, int K, int N)
{
    A += (size_t)blockIdx.z * sA;
    B += (size_t)blockIdx.z * sB;
    C += (size_t)blockIdx.z * sC;
    const float* Ad = (EPI == 2) ? (Add + (size_t)blockIdx.z * sAdd) : nullptr;

    __shared__ __align__(16) float As[2][128 * ASTR];
    __shared__ __align__(16) float Bs[2][16 * BSTR];

    const int tid = threadIdx.x, lane = tid & 31, warp = tid >> 5;
    const int gid = lane >> 2, tig = lane & 3;
    const int wm = (warp >> 2) * 64, wn = (warp & 3) * 32;
    const int bm = blockIdx.y * 128, bn = blockIdx.x * 128;

    const int arow = tid >> 1, acol = (tid & 1) * 8;
    const int brow = tid >> 4, bcol = (tid & 15) * 8;

    const float* Ap = A + (size_t)(bm + arow) * lda + acol;
    const float* Bp = B + (size_t)brow * N + bn + bcol;
    const int apred = ((bm + arow) < M) ? 16 : 0;

    float acc[4][4][4];
    #pragma unroll
    for (int mi = 0; mi < 4; mi++)
        #pragma unroll
        for (int ni = 0; ni < 4; ni++)
            #pragma unroll
            for (int r = 0; r < 4; r++) acc[mi][ni][r] = 0.f;

    const int nk = K >> 4;

    {
        unsigned int sa = (unsigned int)__cvta_generic_to_shared(&As[0][arow * ASTR + acol]);
        asm volatile("cp.async.ca.shared.global [%0], [%1], 16, %2;\n" :: "r"(sa), "l"(Ap), "r"(apred));
        asm volatile("cp.async.ca.shared.global [%0], [%1], 16, %2;\n" :: "r"(sa + 16), "l"(Ap + 4), "r"(apred));
        unsigned int sb = (unsigned int)__cvta_generic_to_shared(&Bs[0][brow * BSTR + bcol]);
        asm volatile("cp.async.ca.shared.global [%0], [%1], 16;\n" :: "r"(sb), "l"(Bp));
        asm volatile("cp.async.ca.shared.global [%0], [%1], 16;\n" :: "r"(sb + 16), "l"(Bp + 4));
        asm volatile("cp.async.commit_group;\n");
    }

    for (int kb = 0; kb < nk; kb++) {
        const int cur = kb & 1;
        if (kb + 1 < nk) {
            const int nxt = cur ^ 1;
            const float* ga = Ap + (kb + 1) * 16;
            unsigned int sa = (unsigned int)__cvta_generic_to_shared(&As[nxt][arow * ASTR + acol]);
            asm volatile("cp.async.ca.shared.global [%0], [%1], 16, %2;\n" :: "r"(sa), "l"(ga), "r"(apred));
            asm volatile("cp.async.ca.shared.global [%0], [%1], 16, %2;\n" :: "r"(sa + 16), "l"(ga + 4), "r"(apred));
            const float* gb = Bp + (size_t)(kb + 1) * 16 * N;
            unsigned int sb = (unsigned int)__cvta_generic_to_shared(&Bs[nxt][brow * BSTR + bcol]);
            asm volatile("cp.async.ca.shared.global [%0], [%1], 16;\n" :: "r"(sb), "l"(gb));
            asm volatile("cp.async.ca.shared.global [%0], [%1], 16;\n" :: "r"(sb + 16), "l"(gb + 4));
            asm volatile("cp.async.commit_group;\n");
            asm volatile("cp.async.wait_group 1;\n");
        } else {
            asm volatile("cp.async.wait_group 0;\n");
        }
        __syncthreads();

        #pragma unroll
        for (int ks = 0; ks < 2; ks++) {
            const int k0 = ks * 8;
            unsigned int af[4][4];
            unsigned int bf[4][2];
            #pragma unroll
            for (int mi = 0; mi < 4; mi++) {
                const float* ab = &As[cur][(wm + mi * 16 + gid) * ASTR + k0 + tig];
                af[mi][0] = __float_as_uint(ab[0]);
                af[mi][2] = __float_as_uint(ab[4]);
                af[mi][1] = __float_as_uint(ab[8 * ASTR]);
                af[mi][3] = __float_as_uint(ab[8 * ASTR + 4]);
            }
            #pragma unroll
            for (int ni = 0; ni < 4; ni++) {
                const float* bb = &Bs[cur][(k0 + tig) * BSTR + wn + ni * 8 + gid];
                float b0 = bb[0];
                float b1 = bb[4 * BSTR];
                if (CVTB) {
                    asm("cvt.rna.tf32.f32 %0, %1;" : "=r"(bf[ni][0]) : "f"(b0));
                    asm("cvt.rna.tf32.f32 %0, %1;" : "=r"(bf[ni][1]) : "f"(b1));
                } else {
                    bf[ni][0] = __float_as_uint(b0);
                    bf[ni][1] = __float_as_uint(b1);
                }
            }
            #pragma unroll
            for (int mi = 0; mi < 4; mi++)
                #pragma unroll
                for (int ni = 0; ni < 4; ni++) {
                    asm volatile(
                        "mma.sync.aligned.m16n8k8.row.col.f32.tf32.tf32.f32 "
                        "{%0,%1,%2,%3}, {%4,%5,%6,%7}, {%8,%9}, {%0,%1,%2,%3};\n"
                        : "+f"(acc[mi][ni][0]), "+f"(acc[mi][ni][1]),
                          "+f"(acc[mi][ni][2]), "+f"(acc[mi][ni][3])
                        : "r"(af[mi][0]), "r"(af[mi][1]), "r"(af[mi][2]), "r"(af[mi][3]),
                          "r"(bf[ni][0]), "r"(bf[ni][1]));
                }
        }
        __syncthreads();
    }

    #pragma unroll
    for (int mi = 0; mi < 4; mi++) {
        const int r0 = bm + wm + mi * 16 + gid;
        const int r1 = r0 + 8;
        const bool ok0 = r0 < M, ok1 = r1 < M;
        const float bv0 = (bias && ok0) ? bias[r0] : 0.f;
        const float bv1 = (bias && ok1) ? bias[r1] : 0.f;
        #pragma unroll
        for (int ni = 0; ni < 4; ni++) {
            const int cc = bn + wn + ni * 8 + 2 * tig;
            if (ok0) {
                size_t o = (size_t)r0 * N + cc;
                float v0 = acc[mi][ni][0] + bv0;
                float v1 = acc[mi][ni][1] + bv0;
                if (EPI == 1) { v0 = tf32r(v0); v1 = tf32r(v1); }
                if (EPI == 2) {
                    float2 ad = *(const float2*)&Ad[o];
                    v0 = fmaxf(v0, 0.f) + ad.x;
                    v1 = fmaxf(v1, 0.f) + ad.y;
                }
                *(float2*)&C[o] = make_float2(v0, v1);
            }
            if (ok1) {
                size_t o = (size_t)r1 * N + cc;
                float v0 = acc[mi][ni][2] + bv1;
                float v1 = acc[mi][ni][3] + bv1;
                if (EPI == 1) { v0 = tf32r(v0); v1 = tf32r(v1); }
                if (EPI == 2) {
                    float2 ad = *(const float2*)&Ad[o];
                    v0 = fmaxf(v0, 0.f) + ad.x;
                    v1 = fmaxf(v1, 0.f) + ad.y;
                }
                *(float2*)&C[o] = make_float2(v0, v1);
            }
        }
    }
}

// ---------------- fused im2col + GEMM for the 3x3 offset/mask conv ----------------
// C[216, HWSZ] = om_w[216, 1152] @ col(g_off)[1152, HWSZ] + om_b
// n-tile (128 cols) == one image row h; B tile row r of k-block kb is channel
// c = (kb*16+r)/9 of g_off at image row h+dy shifted by dx, edge-zeroed.
__global__ __launch_bounds__(256, 2) void om_conv_gemm(
    const float* __restrict__ bias, float* __restrict__ C)
{
    const float* A = g_omw;
    const float* Boff = g_off + (size_t)blockIdx.z * CC * HWSZ;
    float* Cb = C + (size_t)blockIdx.z * OMCH * HWSZ;

    __shared__ __align__(16) float As[2][128 * ASTR];
    __shared__ __align__(16) float Bs[2][16 * BSTR];

    const int tid = threadIdx.x, lane = tid & 31, warp = tid >> 5;
    const int gid = lane >> 2, tig = lane & 3;
    const int wm = (warp >> 2) * 64, wn = (warp & 3) * 32;
    const int bm = blockIdx.y * 128;
    const int h = blockIdx.x;            // image row == n-tile
    const int bn = h * 128;

    const int arow = tid >> 1, acol = (tid & 1) * 8;
    const float* Ap = A + (size_t)(bm + arow) * KBIG + acol;
    const int apred = ((bm + arow) < OMCH) ? 16 : 0;

    // B loader mapping: row r = tid>>4 (0..15), col base cj = tid&15, 8 cols stride 16
    const int r  = tid >> 4;
    const int cj = tid & 15;

    float acc[4][4][4];
    #pragma unroll
    for (int mi = 0; mi < 4; mi++)
        #pragma unroll
        for (int ni = 0; ni < 4; ni++)
            #pragma unroll
            for (int q = 0; q < 4; q++) acc[mi][ni][q] = 0.f;

    const int nk = KBIG / 16;   // 72

    // ---- B stage loader (predicated 4B cp.async, zero-fill OOB) ----
    auto load_b = [&](int kb, int buf) {
        int ck = kb * 16 + r;
        int c  = ck / 9;
        int kk = ck - 9 * c;
        int dy = kk / 3 - 1;
        int dx = kk - (kk / 3) * 3 - 1;
        int hs = h + dy;
        bool rowok = (unsigned)hs < 128u;
        const float* src = Boff + (size_t)c * HWSZ + hs * 128 + dx;
        unsigned int sdst = (unsigned int)__cvta_generic_to_shared(&Bs[buf][r * BSTR + cj]);
        #pragma unroll
        for (int j = 0; j < 8; j++) {
            int n = cj + j * 16;
            int ws = n + dx;
            int p = (rowok && (unsigned)ws < 128u) ? 4 : 0;
            asm volatile("cp.async.ca.shared.global [%0], [%1], 4, %2;\n"
                         :: "r"(sdst + j * 64), "l"(src + n), "r"(p));
        }
    };
    auto load_a = [&](int kb, int buf) {
        const float* ga = Ap + kb * 16;
        unsigned int sa = (unsigned int)__cvta_generic_to_shared(&As[buf][arow * ASTR + acol]);
        asm volatile("cp.async.ca.shared.global [%0], [%1], 16, %2;\n" :: "r"(sa), "l"(ga), "r"(apred));
        asm volatile("cp.async.ca.shared.global [%0], [%1], 16, %2;\n" :: "r"(sa + 16), "l"(ga + 4), "r"(apred));
    };

    load_a(0, 0);
    load_b(0, 0);
    asm volatile("cp.async.commit_group;\n");

    for (int kb = 0; kb < nk; kb++) {
        const int cur = kb & 1;
        if (kb + 1 < nk) {
            load_a(kb + 1, cur ^ 1);
            load_b(kb + 1, cur ^ 1);
            asm volatile("cp.async.commit_group;\n");
            asm volatile("cp.async.wait_group 1;\n");
        } else {
            asm volatile("cp.async.wait_group 0;\n");
        }
        __syncthreads();

        #pragma unroll
        for (int ks = 0; ks < 2; ks++) {
            const int k0 = ks * 8;
            unsigned int af[4][4];
            unsigned int bf[4][2];
            #pragma unroll
            for (int mi = 0; mi < 4; mi++) {
                const float* ab = &As[cur][(wm + mi * 16 + gid) * ASTR + k0 + tig];
                af[mi][0] = __float_as_uint(ab[0]);
                af[mi][2] = __float_as_uint(ab[4]);
                af[mi][1] = __float_as_uint(ab[8 * ASTR]);
                af[mi][3] = __float_as_uint(ab[8 * ASTR + 4]);
            }
            #pragma unroll
            for (int ni = 0; ni < 4; ni++) {
                const float* bb = &Bs[cur][(k0 + tig) * BSTR + wn + ni * 8 + gid];
                bf[ni][0] = __float_as_uint(bb[0]);
                bf[ni][1] = __float_as_uint(bb[4 * BSTR]);
            }
            #pragma unroll
            for (int mi = 0; mi < 4; mi++)
                #pragma unroll
                for (int ni = 0; ni < 4; ni++) {
                    asm volatile(
                        "mma.sync.aligned.m16n8k8.row.col.f32.tf32.tf32.f32 "
                        "{%0,%1,%2,%3}, {%4,%5,%6,%7}, {%8,%9}, {%0,%1,%2,%3};\n"
                        : "+f"(acc[mi][ni][0]), "+f"(acc[mi][ni][1]),
                          "+f"(acc[mi][ni][2]), "+f"(acc[mi][ni][3])
                        : "r"(af[mi][0]), "r"(af[mi][1]), "r"(af[mi][2]), "r"(af[mi][3]),
                          "r"(bf[ni][0]), "r"(bf[ni][1]));
                }
        }
        __syncthreads();
    }

    #pragma unroll
    for (int mi = 0; mi < 4; mi++) {
        const int r0 = bm + wm + mi * 16 + gid;
        const int r1 = r0 + 8;
        const bool ok0 = r0 < OMCH, ok1 = r1 < OMCH;
        const float bv0 = ok0 ? bias[r0] : 0.f;
        const float bv1 = ok1 ? bias[r1] : 0.f;
        #pragma unroll
        for (int ni = 0; ni < 4; ni++) {
            const int cc = bn + wn + ni * 8 + 2 * tig;
            if (ok0) {
                size_t o = (size_t)r0 * HWSZ + cc;
                *(float2*)&Cb[o] = make_float2(acc[mi][ni][0] + bv0, acc[mi][ni][1] + bv0);
            }
            if (ok1) {
                size_t o = (size_t)r1 * HWSZ + cc;
                *(float2*)&Cb[o] = make_float2(acc[mi][ni][2] + bv1, acc[mi][ni][3] + bv1);
            }
        }
    }
}

// ---------------- launch ----------------
extern "C" void kernel_launch(void* const* d_in, const int* in_sizes, int n_in,
                              void* d_out, int out_size) {
    const float* feat_l  = (const float*)d_in[0];
    const float* feat_s  = (const float*)d_in[1];
    const float* atten_w = (const float*)d_in[2];
    const float* atten_b = (const float*)d_in[3];
    const float* bn_g    = (const float*)d_in[4];
    const float* bn_b    = (const float*)d_in[5];
    const float* bn_m    = (const float*)d_in[6];
    const float* bn_v    = (const float*)d_in[7];
    const float* fsm_w   = (const float*)d_in[8];
    const float* fsm_b   = (const float*)d_in[9];
    const float* om_b    = (const float*)d_in[12];
    const float* dcn_b   = (const float*)d_in[14];
    float* out = (float*)d_out;

    float *p_armW, *p_cat, *p_off, *p_om, *p_S, *p_offw, *p_dcnw;
    cudaGetSymbolAddress((void**)&p_armW, g_armW);
    cudaGetSymbolAddress((void**)&p_cat,  g_cat);
    cudaGetSymbolAddress((void**)&p_off,  g_off);
    cudaGetSymbolAddress((void**)&p_om,   g_om);
    cudaGetSymbolAddress((void**)&p_S,    g_S);
    cudaGetSymbolAddress((void**)&p_offw, g_offw);
    cudaGetSymbolAddress((void**)&p_dcnw, g_dcnw);

    // 1) SE gate + weight rounding
    pool_kernel<<<BATCH * CC, 256>>>(feat_l);
    atten_kernel<<<1, 256>>>(atten_w, atten_b, bn_g, bn_b, bn_m, bn_v);
    armw_kernel<<<128, 256>>>(fsm_w);
    roundw_kernel<<<(OMCH * KBIG + 255) / 256, 256>>>(
        (const float*)d_in[11], (const float*)d_in[13], (const float*)d_in[10]);

    // 2) upsample feat_s into cat rows 128..255
    upsample_kernel<<<(BATCH * CC * HWSZ + 255) / 256, 256>>>(feat_s);

    // 3) feat_arm = (fsm_w*scale) @ feat_l + fsm_b  -> cat rows 0..127 (full precision)
    mma_gemm<0, 1><<<dim3(HWSZ / 128, 1, BATCH), 256>>>(
        p_armW, CC, (size_t)CC * CC,
        feat_l, (size_t)CC * HWSZ,
        fsm_b,
        p_cat, (size_t)2 * CC * HWSZ,
        nullptr, 0,
        CC, CC, HWSZ);

    // 4) off_feat = off_w @ [feat_arm; feat_up]  (tf32-rounded output)
    mma_gemm<1, 1><<<dim3(HWSZ / 128, 1, BATCH), 256>>>(
        p_offw, 2 * CC, 0,
        p_cat, (size_t)2 * CC * HWSZ,
        nullptr,
        p_off, (size_t)CC * HWSZ,
        nullptr, 0,
        CC, 2 * CC, HWSZ);

    // 5) fused im2col + 3x3 conv GEMM (M=216, K=1152)
    om_conv_gemm<<<dim3(128, 2, BATCH), 256>>>(om_b, p_om);

    // 6) bilinear sample + mask -> S (tf32-rounded)
    sample_kernel<<<(BATCH * DGRP * KPTS * HWSZ + 255) / 256, 256>>>();

    // 7) DCN GEMM + relu + bias + feat_arm -> out
    mma_gemm<2, 0><<<dim3(HWSZ / 128, 1, BATCH), 256>>>(
        p_dcnw, KBIG, 0,
        p_S, (size_t)KBIG * HWSZ,
        dcn_b,
        out, (size_t)CC * HWSZ,
        p_cat, (size_t)2 * CC * HWSZ,
        CC, KBIG, HWSZ);
}

// round 7
// speedup vs baseline: 3.4614x; 1.4500x over previous
#include <cuda_runtime.h>
#include <cuda_fp16.h>
#include <cstdint>
#include <stdint.h>
#include <math.h>

// ---------------- problem constants ----------------
#define BATCH 2
#define CC    128
#define HWSZ  16384         // 128*128
#define HS    64
#define DGRP  8
#define CG    16
#define KPTS  9
#define OMCH  216           // DG*3*KK
#define KBIG  1152          // CC*9

// ---------------- scratch ----------------
__device__ float g_pooled[BATCH * CC];
__device__ float g_scale [BATCH * CC];
__device__ float g_cat   [(size_t)BATCH * 2 * CC * HWSZ];     // fp32: rows 0..127 feat_arm, 128..255 feat_up
__device__ float g_om    [(size_t)BATCH * OMCH * HWSZ];       // fp32 offsets/mask

__device__ __align__(16) __half g_armWh[BATCH * CC * CC];     // fp16 A matrices
__device__ __align__(16) __half g_offwh[CC * 2 * CC];
__device__ __align__(16) __half g_omwh [OMCH * KBIG];
__device__ __align__(16) __half g_dcnwh[CC * KBIG];

// fp16 B operands, k-pair-interleaved word layout: word[kp][n] = (half(2kp,n), half(2kp+1,n))
__device__ __align__(16) __half g_flh  [(size_t)BATCH * CC * HWSZ];       // feat_l
__device__ __align__(16) __half g_cath [(size_t)BATCH * 2 * CC * HWSZ];   // [feat_arm; feat_up]
__device__ __align__(16) __half g_Sh   [(size_t)BATCH * KBIG * HWSZ];     // sampled DCN input
// plain fp16 [c][h][w] for the fused om conv loader
__device__ __align__(16) __half g_offh [(size_t)BATCH * CC * HWSZ];

// ---------------- small kernels ----------------
__global__ void pool_kernel(const float* __restrict__ x) {
    int bc = blockIdx.x;
    const float4* p = (const float4*)(x + (size_t)bc * HWSZ);
    float s = 0.f;
    for (int i = threadIdx.x; i < HWSZ / 4; i += 256) {
        float4 v = p[i];
        s += v.x + v.y + v.z + v.w;
    }
    __shared__ float sh[256];
    sh[threadIdx.x] = s;
    __syncthreads();
    for (int o = 128; o > 0; o >>= 1) {
        if (threadIdx.x < o) sh[threadIdx.x] += sh[threadIdx.x + o];
        __syncthreads();
    }
    if (threadIdx.x == 0) g_pooled[bc] = sh[0] * (1.0f / HWSZ);
}

__global__ void atten_kernel(const float* __restrict__ aw, const float* __restrict__ ab,
                             const float* __restrict__ bg, const float* __restrict__ bb,
                             const float* __restrict__ bm, const float* __restrict__ bv) {
    int t = threadIdx.x;
    int b = t >> 7, o = t & 127;
    float a = ab[o];
    const float* pr = g_pooled + b * CC;
    const float* wr = aw + o * CC;
    #pragma unroll 4
    for (int c = 0; c < CC; c++) a += pr[c] * wr[c];
    a = (a - bm[o]) * rsqrtf(bv[o] + 1e-5f) * bg[o] + bb[o];
    g_scale[t] = 1.f + 1.f / (1.f + expf(-a));
}

__global__ void armw_kernel(const float* __restrict__ fsm_w) {
    int i = blockIdx.x * blockDim.x + threadIdx.x;
    int c = i & 127;
    int bo = i >> 7;
    int o = bo & 127;
    int b = bo >> 7;
    g_armWh[i] = __float2half(fsm_w[o * CC + c] * g_scale[b * CC + c]);
}

__global__ void whpack_kernel(const float* __restrict__ om_w,
                              const float* __restrict__ dcn_w,
                              const float* __restrict__ off_w) {
    int i = blockIdx.x * blockDim.x + threadIdx.x;
    if (i < OMCH * KBIG) g_omwh[i] = __float2half(om_w[i]);
    if (i < CC * KBIG)   g_dcnwh[i] = __float2half(dcn_w[i]);
    if (i < CC * 2 * CC) g_offwh[i] = __float2half(off_w[i]);
}

// feat_l fp32 -> fp16 interleaved
__global__ void fl2h_kernel(const float* __restrict__ fl) {
    int i = blockIdx.x * blockDim.x + threadIdx.x;
    if (i >= BATCH * CC * HWSZ) return;
    int n = i & (HWSZ - 1);
    int bc = i >> 14;
    int b = bc >> 7, c = bc & 127;
    g_flh[((size_t)b * (CC / 2) + (c >> 1)) * (2 * HWSZ) + n * 2 + (c & 1)] = __float2half(fl[i]);
}

__global__ void upsample_kernel(const float* __restrict__ fs) {
    int i = blockIdx.x * blockDim.x + threadIdx.x;
    if (i >= BATCH * CC * HWSZ) return;
    int n = i & (HWSZ - 1);
    int bc = i >> 14;
    int b = bc >> 7, c = bc & 127;
    int h = n >> 7, w = n & 127;
    float fy = (h * 63.0f) / 127.0f;
    float fx = (w * 63.0f) / 127.0f;
    int y0 = (int)floorf(fy); float wy = fy - y0; int y1 = min(y0 + 1, 63);
    int x0 = (int)floorf(fx); float wx = fx - x0; int x1 = min(x0 + 1, 63);
    const float* p = fs + (size_t)bc * (HS * HS);
    float v = p[y0 * HS + x0] * (1.f - wy) * (1.f - wx)
            + p[y0 * HS + x1] * (1.f - wy) * wx
            + p[y1 * HS + x0] * wy * (1.f - wx)
            + p[y1 * HS + x1] * wy * wx;
    g_cat[((size_t)b * 2 * CC + CC + c) * HWSZ + n] = v;
    // fp16 interleaved copy: per batch 2C channels = 128 kp rows; feat_up = kp rows 64..127
    g_cath[((size_t)b * CC + (CC >> 1) + (c >> 1)) * (2 * HWSZ) + n * 2 + (c & 1)] = __float2half(v);
}

__global__ void sample_kernel() {
    int i = blockIdx.x * blockDim.x + threadIdx.x;
    if (i >= BATCH * DGRP * KPTS * HWSZ) return;
    int n = i & (HWSZ - 1);
    int t = i >> 14;
    int k = t % KPTS; t /= KPTS;
    int g = t & 7;
    int b = t >> 3;
    int h = n >> 7, w = n & 127;

    const float* om = g_om + (size_t)b * OMCH * HWSZ;
    int gk = g * KPTS + k;
    float offy = om[(size_t)gk * HWSZ + n];
    float offx = om[(size_t)(72 + gk) * HWSZ + n];
    float mm   = om[(size_t)(144 + gk) * HWSZ + n];
    mm = 1.f / (1.f + expf(-mm));

    float py = (float)(h + k / 3 - 1) + offy;
    float px = (float)(w + k % 3 - 1) + offx;
    float y0f = floorf(py), x0f = floorf(px);
    float ly = py - y0f, lx = px - x0f;
    int y0 = (int)y0f, x0 = (int)x0f;
    int y1 = y0 + 1, x1 = x0 + 1;
    bool vy0 = (y0 >= 0 && y0 < 128), vy1 = (y1 >= 0 && y1 < 128);
    bool vx0 = (x0 >= 0 && x0 < 128), vx1 = (x1 >= 0 && x1 < 128);
    int cy0 = min(max(y0, 0), 127), cy1 = min(max(y1, 0), 127);
    int cx0 = min(max(x0, 0), 127), cx1 = min(max(x1, 0), 127);
    float w00 = (vy0 && vx0) ? (1.f - ly) * (1.f - lx) * mm : 0.f;
    float w01 = (vy0 && vx1) ? (1.f - ly) * lx * mm : 0.f;
    float w10 = (vy1 && vx0) ? ly * (1.f - lx) * mm : 0.f;
    float w11 = (vy1 && vx1) ? ly * lx * mm : 0.f;
    int i00 = (cy0 << 7) + cx0, i01 = (cy0 << 7) + cx1;
    int i10 = (cy1 << 7) + cx0, i11 = (cy1 << 7) + cx1;

    const float* fu = g_cat + ((size_t)b * 2 * CC + CC + g * CG) * HWSZ;
    #pragma unroll
    for (int c = 0; c < CG; c++) {
        const float* p = fu + (size_t)c * HWSZ;
        float v = w00 * p[i00] + w01 * p[i01] + w10 * p[i10] + w11 * p[i11];
        int r = g * 144 + c * 9 + k;     // GEMM k-row
        g_Sh[((size_t)b * (KBIG / 2) + (r >> 1)) * (2 * HWSZ) + n * 2 + (r & 1)] = __float2half(v);
    }
}

// ---------------- FP16 tensor-core GEMM ----------------
// C[M,N] = A[M,K] @ B[K,N], BM=BN=128, BK=32 (halves), 256 threads, 8 warps 2x4,
// mma.sync.m16n8k16.f32.f16.f16.f32, cp.async double-buffered.
// A: fp16 row-major (lda halves). B: fp16 k-pair-interleaved words [K/2][N].
// EPI 2: C = relu(acc+bias) + Add (fp32)
// EPI 3: C = acc+bias (fp32) AND interleaved fp16 to Ch
// EPI 4: interleaved-input -> plain fp16 out Ch[r*N+n]
// EPI 5: fp32 out only
#define AHSTR 40   // halves per A smem row (32 data + 8 pad) = 80B, word stride 20
#define BWSTR 136  // words per B kp-row: banks 8*tig+gid -> conflict-free

#define HGEMM_CORE()                                                                        \
    for (int ks = 0; ks < 2; ks++) {                                                        \
        unsigned int af[4][4], bf[4][2];                                                    \
        const unsigned int* aw = (const unsigned int*)&As[cur][0];                          \
        _Pragma("unroll")                                                                   \
        for (int mi = 0; mi < 4; mi++) {                                                    \
            int row = wm + mi * 16 + gid;                                                   \
            af[mi][0] = aw[row * 20 + ks * 8 + tig];                                        \
            af[mi][1] = aw[(row + 8) * 20 + ks * 8 + tig];                                  \
            af[mi][2] = aw[row * 20 + ks * 8 + tig + 4];                                    \
            af[mi][3] = aw[(row + 8) * 20 + ks * 8 + tig + 4];                              \
        }                                                                                   \
        _Pragma("unroll")                                                                   \
        for (int ni = 0; ni < 4; ni++) {                                                    \
            int col = wn + ni * 8 + gid;                                                    \
            bf[ni][0] = Bs[cur][(ks * 8 + tig) * BWSTR + col];                              \
            bf[ni][1] = Bs[cur][(ks * 8 + tig + 4) * BWSTR + col];                          \
        }                                                                                   \
        _Pragma("unroll")                                                                   \
        for (int mi = 0; mi < 4; mi++)                                                      \
            _Pragma("unroll")                                                               \
            for (int ni = 0; ni < 4; ni++) {                                                \
                asm volatile(                                                               \
                    "mma.sync.aligned.m16n8k16.row.col.f32.f16.f16.f32 "                    \
                    "{%0,%1,%2,%3}, {%4,%5,%6,%7}, {%8,%9}, {%0,%1,%2,%3};\n"               \
                    : "+f"(acc[mi][ni][0]), "+f"(acc[mi][ni][1]),                           \
                      "+f"(acc[mi][ni][2]), "+f"(acc[mi][ni][3])                            \
                    : "r"(af[mi][0]), "r"(af[mi][1]), "r"(af[mi][2]), "r"(af[mi][3]),       \
                      "r"(bf[ni][0]), "r"(bf[ni][1]));                                      \
            }                                                                               \
    }

template<int EPI>
__global__ __launch_bounds__(256, 2) void hgemm(
    const __half* __restrict__ A, int lda, size_t sA,
    const unsigned int* __restrict__ Bw, size_t sB,
    const float* __restrict__ bias,
    float* __restrict__ C, size_t sC,
    __half* __restrict__ Ch, size_t sCh,
    const float* __restrict__ Add, size_t sAdd,
    int M, int K, int N)
{
    const int bz = blockIdx.z;
    A += (size_t)bz * sA;
    Bw += (size_t)bz * sB;

    __shared__ __align__(16) __half As[2][128 * AHSTR];
    __shared__ __align__(16) unsigned int Bs[2][16 * BWSTR];

    const int tid = threadIdx.x, lane = tid & 31, warp = tid >> 5;
    const int gid = lane >> 2, tig = lane & 3;
    const int wm = (warp >> 2) * 64, wn = (warp & 3) * 32;
    const int bm = blockIdx.y * 128, bn = blockIdx.x * 128;

    // A loader: thread t -> row t>>1, 16-half chunk (t&1)
    const int arow = tid >> 1, ac = (tid & 1) * 16;
    const __half* Ap = A + (size_t)(bm + arow) * lda + ac;
    const int apred = ((bm + arow) < M) ? 16 : 0;
    // B loader: row t>>4 (kp), 8-word chunk (t&15)*8
    const int brow = tid >> 4, bcw = (tid & 15) * 8;
    const unsigned int* Bp = Bw + (size_t)brow * N + bn + bcw;

    float acc[4][4][4];
    #pragma unroll
    for (int mi = 0; mi < 4; mi++)
        #pragma unroll
        for (int ni = 0; ni < 4; ni++)
            #pragma unroll
            for (int q = 0; q < 4; q++) acc[mi][ni][q] = 0.f;

    const int nk = K >> 5;

    auto stage = [&](int kb, int buf) {
        unsigned int sa = (unsigned int)__cvta_generic_to_shared(&As[buf][arow * AHSTR + ac]);
        const __half* ga = Ap + kb * 32;
        asm volatile("cp.async.ca.shared.global [%0], [%1], 16, %2;\n" :: "r"(sa), "l"(ga), "r"(apred));
        asm volatile("cp.async.ca.shared.global [%0], [%1], 16, %2;\n" :: "r"(sa + 16), "l"(ga + 8), "r"(apred));
        unsigned int sb = (unsigned int)__cvta_generic_to_shared(&Bs[buf][brow * BWSTR + bcw]);
        const unsigned int* gb = Bp + (size_t)kb * 16 * N;
        asm volatile("cp.async.ca.shared.global [%0], [%1], 16;\n" :: "r"(sb), "l"(gb));
        asm volatile("cp.async.ca.shared.global [%0], [%1], 16;\n" :: "r"(sb + 16), "l"(gb + 4));
        asm volatile("cp.async.commit_group;\n");
    };

    stage(0, 0);
    for (int kb = 0; kb < nk; kb++) {
        const int cur = kb & 1;
        if (kb + 1 < nk) {
            stage(kb + 1, cur ^ 1);
            asm volatile("cp.async.wait_group 1;\n");
        } else {
            asm volatile("cp.async.wait_group 0;\n");
        }
        __syncthreads();
        HGEMM_CORE();
        __syncthreads();
    }

    // epilogue
    #pragma unroll
    for (int mi = 0; mi < 4; mi++) {
        const int r0 = bm + wm + mi * 16 + gid;
        const int r1 = r0 + 8;
        const bool ok0 = r0 < M, ok1 = r1 < M;
        const float bv0 = (bias && ok0) ? bias[r0] : 0.f;
        const float bv1 = (bias && ok1) ? bias[r1] : 0.f;
        #pragma unroll
        for (int ni = 0; ni < 4; ni++) {
            const int cc = bn + wn + ni * 8 + 2 * tig;
            #pragma unroll
            for (int half_m = 0; half_m < 2; half_m++) {
                const int r = half_m ? r1 : r0;
                if (!(half_m ? ok1 : ok0)) continue;
                float v0 = acc[mi][ni][half_m * 2 + 0] + (half_m ? bv1 : bv0);
                float v1 = acc[mi][ni][half_m * 2 + 1] + (half_m ? bv1 : bv0);
                if (EPI == 2) {
                    size_t o = (size_t)bz * sC + (size_t)r * N + cc;
                    const float2 ad = *(const float2*)&Add[(size_t)bz * sAdd + (size_t)r * N + cc];
                    C[o] = fmaxf(v0, 0.f) + ad.x;
                    C[o + 1] = fmaxf(v1, 0.f) + ad.y;
                } else if (EPI == 3) {
                    size_t o = (size_t)bz * sC + (size_t)r * N + cc;
                    *(float2*)&C[o] = make_float2(v0, v1);
                    size_t oh = (size_t)bz * sCh + ((size_t)(r >> 1) * N + cc) * 2 + (r & 1);
                    Ch[oh] = __float2half(v0);
                    Ch[oh + 2] = __float2half(v1);
                } else if (EPI == 4) {
                    size_t oh = (size_t)bz * sCh + (size_t)r * N + cc;
                    Ch[oh] = __float2half(v0);
                    Ch[oh + 1] = __float2half(v1);
                } else {
                    size_t o = (size_t)bz * sC + (size_t)r * N + cc;
                    *(float2*)&C[o] = make_float2(v0, v1);
                }
            }
        }
    }
}

// ---------------- fused im2col + fp16 GEMM for the 3x3 offset/mask conv ----------------
// C[216, HWSZ] = om_w @ col(off_feat) + om_b ; B built on the fly from g_offh.
__global__ __launch_bounds__(256, 2) void hgemm_om(
    const float* __restrict__ bias, float* __restrict__ C)
{
    const int bz = blockIdx.z;
    const __half* A = g_omwh;
    const __half* Boff = g_offh + (size_t)bz * CC * HWSZ;
    float* Cb = C + (size_t)bz * OMCH * HWSZ;

    __shared__ __align__(16) __half As[2][128 * AHSTR];
    __shared__ __align__(16) unsigned int Bs[2][16 * BWSTR];

    const int tid = threadIdx.x, lane = tid & 31, warp = tid >> 5;
    const int gid = lane >> 2, tig = lane & 3;
    const int wm = (warp >> 2) * 64, wn = (warp & 3) * 32;
    const int bm = blockIdx.y * 128;
    const int h = blockIdx.x;          // image row == n-tile
    const int bn = h * 128;

    const int arow = tid >> 1, ac = (tid & 1) * 16;
    const __half* Ap = A + (size_t)(bm + arow) * KBIG + ac;
    const int apred = ((bm + arow) < OMCH) ? 16 : 0;

    // B loader: row r = tid>>3 (0..31 = k halves), col base ct = tid&7, 16 cols stride 8
    const int r  = tid >> 3;
    const int ct = tid & 7;

    float acc[4][4][4];
    #pragma unroll
    for (int mi = 0; mi < 4; mi++)
        #pragma unroll
        for (int ni = 0; ni < 4; ni++)
            #pragma unroll
            for (int q = 0; q < 4; q++) acc[mi][ni][q] = 0.f;

    const int nk = KBIG / 32;   // 36
    __half bv[16];

    auto load_a = [&](int kb, int buf) {
        unsigned int sa = (unsigned int)__cvta_generic_to_shared(&As[buf][arow * AHSTR + ac]);
        const __half* ga = Ap + kb * 32;
        asm volatile("cp.async.ca.shared.global [%0], [%1], 16, %2;\n" :: "r"(sa), "l"(ga), "r"(apred));
        asm volatile("cp.async.ca.shared.global [%0], [%1], 16, %2;\n" :: "r"(sa + 16), "l"(ga + 8), "r"(apred));
        asm volatile("cp.async.commit_group;\n");
    };
    auto load_b_regs = [&](int kb) {
        int ck = kb * 32 + r;
        int c  = ck / 9;
        int kk = ck - 9 * c;
        int dy = kk / 3 - 1;
        int dx = kk - (kk / 3) * 3 - 1;
        int hs = h + dy;
        bool rowok = (unsigned)hs < 128u;
        const __half* src = Boff + (size_t)c * HWSZ + hs * 128;
        #pragma unroll
        for (int j = 0; j < 16; j++) {
            int n = ct + j * 8;
            int ws = n + dx;
            bv[j] = (rowok && (unsigned)ws < 128u) ? src[ws] : __float2half(0.f);
        }
    };
    auto sts_b = [&](int buf) {
        __half* bsh = (__half*)&Bs[buf][0];
        int base = (r >> 1) * (BWSTR * 2) + (r & 1);
        #pragma unroll
        for (int j = 0; j < 16; j++) {
            int n = ct + j * 8;
            bsh[base + n * 2] = bv[j];
        }
    };

    load_a(0, 0);
    load_b_regs(0);
    asm volatile("cp.async.wait_group 0;\n");
    sts_b(0);
    __syncthreads();

    for (int kb = 0; kb < nk; kb++) {
        const int cur = kb & 1;
        if (kb + 1 < nk) {
            load_a(kb + 1, cur ^ 1);
            load_b_regs(kb + 1);
        }
        HGEMM_CORE();
        if (kb + 1 < nk) {
            asm volatile("cp.async.wait_group 0;\n");
            __syncthreads();          // all warps finished reading cur stage
            sts_b(cur ^ 1);
        }
        __syncthreads();
    }

    #pragma unroll
    for (int mi = 0; mi < 4; mi++) {
        const int r0 = bm + wm + mi * 16 + gid;
        const int r1 = r0 + 8;
        const bool ok0 = r0 < OMCH, ok1 = r1 < OMCH;
        const float bv0 = ok0 ? bias[r0] : 0.f;
        const float bv1 = ok1 ? bias[r1] : 0.f;
        #pragma unroll
        for (int ni = 0; ni < 4; ni++) {
            const int cc = bn + wn + ni * 8 + 2 * tig;
            if (ok0) {
                size_t o = (size_t)r0 * HWSZ + cc;
                *(float2*)&Cb[o] = make_float2(acc[mi][ni][0] + bv0, acc[mi][ni][1] + bv0);
            }
            if (ok1) {
                size_t o = (size_t)r1 * HWSZ + cc;
                *(float2*)&Cb[o] = make_float2(acc[mi][ni][2] + bv1, acc[mi][ni][3] + bv1);
            }
        }
    }
}

// ---------------- launch ----------------
extern "C" void kernel_launch(void* const* d_in, const int* in_sizes, int n_in,
                              void* d_out, int out_size) {
    const float* feat_l  = (const float*)d_in[0];
    const float* feat_s  = (const float*)d_in[1];
    const float* atten_w = (const float*)d_in[2];
    const float* atten_b = (const float*)d_in[3];
    const float* bn_g    = (const float*)d_in[4];
    const float* bn_b    = (const float*)d_in[5];
    const float* bn_m    = (const float*)d_in[6];
    const float* bn_v    = (const float*)d_in[7];
    const float* fsm_w   = (const float*)d_in[8];
    const float* fsm_b   = (const float*)d_in[9];
    const float* om_b    = (const float*)d_in[12];
    const float* dcn_b   = (const float*)d_in[14];
    float* out = (float*)d_out;

    float *p_cat, *p_om;
    __half *p_armWh, *p_offwh, *p_dcnwh, *p_flh, *p_cath, *p_Sh, *p_offh;
    cudaGetSymbolAddress((void**)&p_cat,   g_cat);
    cudaGetSymbolAddress((void**)&p_om,    g_om);
    cudaGetSymbolAddress((void**)&p_armWh, g_armWh);
    cudaGetSymbolAddress((void**)&p_offwh, g_offwh);
    cudaGetSymbolAddress((void**)&p_dcnwh, g_dcnwh);
    cudaGetSymbolAddress((void**)&p_flh,   g_flh);
    cudaGetSymbolAddress((void**)&p_cath,  g_cath);
    cudaGetSymbolAddress((void**)&p_Sh,    g_Sh);
    cudaGetSymbolAddress((void**)&p_offh,  g_offh);

    // 1) SE gate + weight fp16 packing + feat_l convert
    pool_kernel<<<BATCH * CC, 256>>>(feat_l);
    atten_kernel<<<1, 256>>>(atten_w, atten_b, bn_g, bn_b, bn_m, bn_v);
    armw_kernel<<<128, 256>>>(fsm_w);
    whpack_kernel<<<(OMCH * KBIG + 255) / 256, 256>>>(
        (const float*)d_in[11], (const float*)d_in[13], (const float*)d_in[10]);
    fl2h_kernel<<<(BATCH * CC * HWSZ + 255) / 256, 256>>>(feat_l);

    // 2) upsample feat_s (fp32 + fp16 interleaved)
    upsample_kernel<<<(BATCH * CC * HWSZ + 255) / 256, 256>>>(feat_s);

    // 3) feat_arm = armW @ feat_l + fsm_b  -> fp32 g_cat rows 0..127 + fp16 g_cath kp 0..63
    hgemm<3><<<dim3(HWSZ / 128, 1, BATCH), 256>>>(
        p_armWh, CC, (size_t)CC * CC,
        (const unsigned int*)p_flh, (size_t)(CC / 2) * HWSZ,
        fsm_b,
        p_cat, (size_t)2 * CC * HWSZ,
        p_cath, (size_t)2 * CC * HWSZ,
        nullptr, 0,
        CC, CC, HWSZ);

    // 4) off_feat = off_w @ [feat_arm; feat_up]  -> fp16 plain g_offh
    hgemm<4><<<dim3(HWSZ / 128, 1, BATCH), 256>>>(
        p_offwh, 2 * CC, 0,
        (const unsigned int*)p_cath, (size_t)CC * HWSZ,
        nullptr,
        nullptr, 0,
        p_offh, (size_t)CC * HWSZ,
        nullptr, 0,
        CC, 2 * CC, HWSZ);

    // 5) fused im2col + 3x3 conv (M=216, K=1152) -> fp32 g_om
    hgemm_om<<<dim3(128, 2, BATCH), 256>>>(om_b, p_om);

    // 6) bilinear sample + mask -> fp16 interleaved g_Sh
    sample_kernel<<<(BATCH * DGRP * KPTS * HWSZ + 255) / 256, 256>>>();

    // 7) DCN GEMM + relu + bias + feat_arm -> out
    hgemm<2><<<dim3(HWSZ / 128, 1, BATCH), 256>>>(
        p_dcnwh, KBIG, 0,
        (const unsigned int*)p_Sh, (size_t)(KBIG / 2) * HWSZ,
        dcn_b,
        out, (size_t)CC * HWSZ,
        nullptr, 0,
        p_cat, (size_t)2 * CC * HWSZ,
        CC, KBIG, HWSZ);
}

// round 8
// speedup vs baseline: 3.8194x; 1.1034x over previous
#include <cuda_runtime.h>
#include <cuda_fp16.h>
#include <cstdint>
#include <stdint.h>
#include <math.h>

// ---------------- problem constants ----------------
#define BATCH 2
#define CC    128
#define HWSZ  16384         // 128*128
#define HS    64
#define DGRP  8
#define CG    16
#define KPTS  9
#define OMCH  216           // DG*3*KK
#define KBIG  1152          // CC*9

// ---------------- scratch ----------------
__device__ float g_pooled[BATCH * CC];
__device__ float g_scale [BATCH * CC];
__device__ float g_cat   [(size_t)BATCH * 2 * CC * HWSZ];     // fp32: rows 0..127 feat_arm, 128..255 feat_up
__device__ float g_om    [(size_t)BATCH * OMCH * HWSZ];       // fp32 offsets/mask

__device__ __align__(16) __half g_armWh[BATCH * CC * CC];     // fp16 A matrices
__device__ __align__(16) __half g_offwh[CC * 2 * CC];
__device__ __align__(16) __half g_omwh [OMCH * KBIG];
__device__ __align__(16) __half g_dcnwh[CC * KBIG];

// fp16 B operands, k-pair-interleaved word layout: word[kp][n] = (half(2kp,n), half(2kp+1,n))
__device__ __align__(16) __half g_flh  [(size_t)BATCH * CC * HWSZ];       // feat_l
__device__ __align__(16) __half g_cath [(size_t)BATCH * 2 * CC * HWSZ];   // [feat_arm; feat_up]
__device__ __align__(16) __half g_Sh   [(size_t)BATCH * KBIG * HWSZ];     // sampled DCN input
// THREE pre-shifted fp16 copies of off_feat: copy ci (dx=ci-1): copy[ci][b][c][h][x] = off[b][c][h][x+dx]
__device__ __align__(16) __half g_offh3[(size_t)3 * BATCH * CC * HWSZ];

// ---------------- small kernels ----------------
__global__ void pool_kernel(const float* __restrict__ x) {
    int bc = blockIdx.x;
    const float4* p = (const float4*)(x + (size_t)bc * HWSZ);
    float s = 0.f;
    for (int i = threadIdx.x; i < HWSZ / 4; i += 256) {
        float4 v = p[i];
        s += v.x + v.y + v.z + v.w;
    }
    __shared__ float sh[256];
    sh[threadIdx.x] = s;
    __syncthreads();
    for (int o = 128; o > 0; o >>= 1) {
        if (threadIdx.x < o) sh[threadIdx.x] += sh[threadIdx.x + o];
        __syncthreads();
    }
    if (threadIdx.x == 0) g_pooled[bc] = sh[0] * (1.0f / HWSZ);
}

__global__ void atten_kernel(const float* __restrict__ aw, const float* __restrict__ ab,
                             const float* __restrict__ bg, const float* __restrict__ bb,
                             const float* __restrict__ bm, const float* __restrict__ bv) {
    int t = threadIdx.x;
    int b = t >> 7, o = t & 127;
    float a = ab[o];
    const float* pr = g_pooled + b * CC;
    const float* wr = aw + o * CC;
    #pragma unroll 4
    for (int c = 0; c < CC; c++) a += pr[c] * wr[c];
    a = (a - bm[o]) * rsqrtf(bv[o] + 1e-5f) * bg[o] + bb[o];
    g_scale[t] = 1.f + 1.f / (1.f + expf(-a));
}

__global__ void armw_kernel(const float* __restrict__ fsm_w) {
    int i = blockIdx.x * blockDim.x + threadIdx.x;
    int c = i & 127;
    int bo = i >> 7;
    int o = bo & 127;
    int b = bo >> 7;
    g_armWh[i] = __float2half(fsm_w[o * CC + c] * g_scale[b * CC + c]);
}

// weight packing + zero the never-written edge columns of g_offh3
__global__ void whpack_kernel(const float* __restrict__ om_w,
                              const float* __restrict__ dcn_w,
                              const float* __restrict__ off_w) {
    int i = blockIdx.x * blockDim.x + threadIdx.x;
    if (i < OMCH * KBIG) g_omwh[i] = __float2half(om_w[i]);
    if (i < CC * KBIG)   g_dcnwh[i] = __float2half(dcn_w[i]);
    if (i < CC * 2 * CC) g_offwh[i] = __float2half(off_w[i]);
    if (i < 2 * BATCH * CC * 128) {
        int e = i & 1;            // 0 -> copy 0 (dx=-1) x=0 ; 1 -> copy 2 (dx=+1) x=127
        int t = i >> 1;
        int h = t & 127; t >>= 7;
        int c = t & 127; t >>= 7;
        int b = t & 1;
        int ci = e ? 2 : 0;
        int x  = e ? 127 : 0;
        g_offh3[(((size_t)ci * BATCH + b) * CC + c) * HWSZ + h * 128 + x] = __float2half(0.f);
    }
}

// fused: feat_l fp32->fp16 interleaved  AND  upsample feat_s (fp32 + fp16 interleaved)
__global__ void prep_kernel(const float* __restrict__ fl, const float* __restrict__ fs) {
    int i = blockIdx.x * blockDim.x + threadIdx.x;
    if (i >= BATCH * CC * HWSZ) return;
    int n = i & (HWSZ - 1);
    int bc = i >> 14;
    int b = bc >> 7, c = bc & 127;
    // feat_l convert
    g_flh[((size_t)b * (CC / 2) + (c >> 1)) * (2 * HWSZ) + n * 2 + (c & 1)] = __float2half(fl[i]);
    // upsample
    int h = n >> 7, w = n & 127;
    float fy = (h * 63.0f) / 127.0f;
    float fx = (w * 63.0f) / 127.0f;
    int y0 = (int)floorf(fy); float wy = fy - y0; int y1 = min(y0 + 1, 63);
    int x0 = (int)floorf(fx); float wx = fx - x0; int x1 = min(x0 + 1, 63);
    const float* p = fs + (size_t)bc * (HS * HS);
    float v = p[y0 * HS + x0] * (1.f - wy) * (1.f - wx)
            + p[y0 * HS + x1] * (1.f - wy) * wx
            + p[y1 * HS + x0] * wy * (1.f - wx)
            + p[y1 * HS + x1] * wy * wx;
    g_cat[((size_t)b * 2 * CC + CC + c) * HWSZ + n] = v;
    g_cath[((size_t)b * CC + (CC >> 1) + (c >> 1)) * (2 * HWSZ) + n * 2 + (c & 1)] = __float2half(v);
}

// bilinear sample + mask -> fp16 interleaved g_Sh ; corners read as fp16 channel-pair words
__global__ void sample_kernel() {
    int i = blockIdx.x * blockDim.x + threadIdx.x;
    if (i >= BATCH * DGRP * KPTS * HWSZ) return;
    int n = i & (HWSZ - 1);
    int t = i >> 14;
    int k = t % KPTS; t /= KPTS;
    int g = t & 7;
    int b = t >> 3;
    int h = n >> 7, w = n & 127;

    const float* om = g_om + (size_t)b * OMCH * HWSZ;
    int gk = g * KPTS + k;
    float offy = om[(size_t)gk * HWSZ + n];
    float offx = om[(size_t)(72 + gk) * HWSZ + n];
    float mm   = om[(size_t)(144 + gk) * HWSZ + n];
    mm = 1.f / (1.f + expf(-mm));

    float py = (float)(h + k / 3 - 1) + offy;
    float px = (float)(w + k % 3 - 1) + offx;
    float y0f = floorf(py), x0f = floorf(px);
    float ly = py - y0f, lx = px - x0f;
    int y0 = (int)y0f, x0 = (int)x0f;
    int y1 = y0 + 1, x1 = x0 + 1;
    bool vy0 = (y0 >= 0 && y0 < 128), vy1 = (y1 >= 0 && y1 < 128);
    bool vx0 = (x0 >= 0 && x0 < 128), vx1 = (x1 >= 0 && x1 < 128);
    int cy0 = min(max(y0, 0), 127), cy1 = min(max(y1, 0), 127);
    int cx0 = min(max(x0, 0), 127), cx1 = min(max(x1, 0), 127);
    float w00 = (vy0 && vx0) ? (1.f - ly) * (1.f - lx) * mm : 0.f;
    float w01 = (vy0 && vx1) ? (1.f - ly) * lx * mm : 0.f;
    float w10 = (vy1 && vx0) ? ly * (1.f - lx) * mm : 0.f;
    float w11 = (vy1 && vx1) ? ly * lx * mm : 0.f;
    int i00 = (cy0 << 7) + cx0, i01 = (cy0 << 7) + cx1;
    int i10 = (cy1 << 7) + cx0, i11 = (cy1 << 7) + cx1;

    // fp16 channel-pair words of feat_up: kp row = 64 + g*8 + cp
    const unsigned int* cw = (const unsigned int*)g_cath + (size_t)b * CC * HWSZ;
    #pragma unroll
    for (int cp = 0; cp < 8; cp++) {
        const unsigned int* rowp = cw + (size_t)(64 + g * 8 + cp) * HWSZ;
        float2 c00 = __half22float2(*(const __half2*)&rowp[i00]);
        float2 c01 = __half22float2(*(const __half2*)&rowp[i01]);
        float2 c10 = __half22float2(*(const __half2*)&rowp[i10]);
        float2 c11 = __half22float2(*(const __half2*)&rowp[i11]);
        float ve = w00 * c00.x + w01 * c01.x + w10 * c10.x + w11 * c11.x;
        float vo = w00 * c00.y + w01 * c01.y + w10 * c10.y + w11 * c11.y;
        int re = g * 144 + (2 * cp) * 9 + k;
        int ro = re + 9;
        g_Sh[((size_t)b * (KBIG / 2) + (re >> 1)) * (2 * HWSZ) + n * 2 + (re & 1)] = __float2half(ve);
        g_Sh[((size_t)b * (KBIG / 2) + (ro >> 1)) * (2 * HWSZ) + n * 2 + (ro & 1)] = __float2half(vo);
    }
}

// ---------------- FP16 tensor-core GEMM ----------------
// BM=BN=128, BK=32 halves, 256 threads, 8 warps 2x4, m16n8k16, cp.async dbuf.
// EPI 2: C = relu(acc+bias) + Add (fp32)
// EPI 3: C = acc+bias (fp32) AND interleaved fp16 to Ch
// EPI 6: off-GEMM: write 3 shifted fp16 copies into g_offh3
#define AHSTR 40   // halves per A smem row; word stride 20
#define BWSTR 136  // words per B kp-row

#define HGEMM_CORE()                                                                        \
    for (int ks = 0; ks < 2; ks++) {                                                        \
        unsigned int af[4][4], bf[4][2];                                                    \
        const unsigned int* aw = (const unsigned int*)&As[cur][0];                          \
        _Pragma("unroll")                                                                   \
        for (int mi = 0; mi < 4; mi++) {                                                    \
            int row = wm + mi * 16 + gid;                                                   \
            af[mi][0] = aw[row * 20 + ks * 8 + tig];                                        \
            af[mi][1] = aw[(row + 8) * 20 + ks * 8 + tig];                                  \
            af[mi][2] = aw[row * 20 + ks * 8 + tig + 4];                                    \
            af[mi][3] = aw[(row + 8) * 20 + ks * 8 + tig + 4];                              \
        }                                                                                   \
        _Pragma("unroll")                                                                   \
        for (int ni = 0; ni < 4; ni++) {                                                    \
            int col = wn + ni * 8 + gid;                                                    \
            bf[ni][0] = Bs[cur][(ks * 8 + tig) * BWSTR + col];                              \
            bf[ni][1] = Bs[cur][(ks * 8 + tig + 4) * BWSTR + col];                          \
        }                                                                                   \
        _Pragma("unroll")                                                                   \
        for (int mi = 0; mi < 4; mi++)                                                      \
            _Pragma("unroll")                                                               \
            for (int ni = 0; ni < 4; ni++) {                                                \
                asm volatile(                                                               \
                    "mma.sync.aligned.m16n8k16.row.col.f32.f16.f16.f32 "                    \
                    "{%0,%1,%2,%3}, {%4,%5,%6,%7}, {%8,%9}, {%0,%1,%2,%3};\n"               \
                    : "+f"(acc[mi][ni][0]), "+f"(acc[mi][ni][1]),                           \
                      "+f"(acc[mi][ni][2]), "+f"(acc[mi][ni][3])                            \
                    : "r"(af[mi][0]), "r"(af[mi][1]), "r"(af[mi][2]), "r"(af[mi][3]),       \
                      "r"(bf[ni][0]), "r"(bf[ni][1]));                                      \
            }                                                                               \
    }

template<int EPI>
__global__ __launch_bounds__(256, 2) void hgemm(
    const __half* __restrict__ A, int lda, size_t sA,
    const unsigned int* __restrict__ Bw, size_t sB,
    const float* __restrict__ bias,
    float* __restrict__ C, size_t sC,
    __half* __restrict__ Ch, size_t sCh,
    const float* __restrict__ Add, size_t sAdd,
    int M, int K, int N)
{
    const int bz = blockIdx.z;
    A += (size_t)bz * sA;
    Bw += (size_t)bz * sB;

    __shared__ __align__(16) __half As[2][128 * AHSTR];
    __shared__ __align__(16) unsigned int Bs[2][16 * BWSTR];

    const int tid = threadIdx.x, lane = tid & 31, warp = tid >> 5;
    const int gid = lane >> 2, tig = lane & 3;
    const int wm = (warp >> 2) * 64, wn = (warp & 3) * 32;
    const int bm = blockIdx.y * 128, bn = blockIdx.x * 128;

    const int arow = tid >> 1, ac = (tid & 1) * 16;
    const __half* Ap = A + (size_t)(bm + arow) * lda + ac;
    const int apred = ((bm + arow) < M) ? 16 : 0;
    const int brow = tid >> 4, bcw = (tid & 15) * 8;
    const unsigned int* Bp = Bw + (size_t)brow * N + bn + bcw;

    float acc[4][4][4];
    #pragma unroll
    for (int mi = 0; mi < 4; mi++)
        #pragma unroll
        for (int ni = 0; ni < 4; ni++)
            #pragma unroll
            for (int q = 0; q < 4; q++) acc[mi][ni][q] = 0.f;

    const int nk = K >> 5;

    auto stage = [&](int kb, int buf) {
        unsigned int sa = (unsigned int)__cvta_generic_to_shared(&As[buf][arow * AHSTR + ac]);
        const __half* ga = Ap + kb * 32;
        asm volatile("cp.async.ca.shared.global [%0], [%1], 16, %2;\n" :: "r"(sa), "l"(ga), "r"(apred));
        asm volatile("cp.async.ca.shared.global [%0], [%1], 16, %2;\n" :: "r"(sa + 16), "l"(ga + 8), "r"(apred));
        unsigned int sb = (unsigned int)__cvta_generic_to_shared(&Bs[buf][brow * BWSTR + bcw]);
        const unsigned int* gb = Bp + (size_t)kb * 16 * N;
        asm volatile("cp.async.ca.shared.global [%0], [%1], 16;\n" :: "r"(sb), "l"(gb));
        asm volatile("cp.async.ca.shared.global [%0], [%1], 16;\n" :: "r"(sb + 16), "l"(gb + 4));
        asm volatile("cp.async.commit_group;\n");
    };

    stage(0, 0);
    for (int kb = 0; kb < nk; kb++) {
        const int cur = kb & 1;
        if (kb + 1 < nk) {
            stage(kb + 1, cur ^ 1);
            asm volatile("cp.async.wait_group 1;\n");
        } else {
            asm volatile("cp.async.wait_group 0;\n");
        }
        __syncthreads();
        HGEMM_CORE();
        __syncthreads();
    }

    #pragma unroll
    for (int mi = 0; mi < 4; mi++) {
        const int r0 = bm + wm + mi * 16 + gid;
        const int r1 = r0 + 8;
        const bool ok0 = r0 < M, ok1 = r1 < M;
        const float bv0 = (bias && ok0) ? bias[r0] : 0.f;
        const float bv1 = (bias && ok1) ? bias[r1] : 0.f;
        #pragma unroll
        for (int ni = 0; ni < 4; ni++) {
            const int cc = bn + wn + ni * 8 + 2 * tig;
            #pragma unroll
            for (int half_m = 0; half_m < 2; half_m++) {
                const int r = half_m ? r1 : r0;
                if (!(half_m ? ok1 : ok0)) continue;
                float v0 = acc[mi][ni][half_m * 2 + 0] + (half_m ? bv1 : bv0);
                float v1 = acc[mi][ni][half_m * 2 + 1] + (half_m ? bv1 : bv0);
                if (EPI == 2) {
                    size_t o = (size_t)bz * sC + (size_t)r * N + cc;
                    const float2 ad = *(const float2*)&Add[(size_t)bz * sAdd + (size_t)r * N + cc];
                    C[o] = fmaxf(v0, 0.f) + ad.x;
                    C[o + 1] = fmaxf(v1, 0.f) + ad.y;
                } else if (EPI == 3) {
                    size_t o = (size_t)bz * sC + (size_t)r * N + cc;
                    *(float2*)&C[o] = make_float2(v0, v1);
                    size_t oh = (size_t)bz * sCh + ((size_t)(r >> 1) * N + cc) * 2 + (r & 1);
                    Ch[oh] = __float2half(v0);
                    Ch[oh + 2] = __float2half(v1);
                } else if (EPI == 6) {
                    // three shifted copies: copy ci (dx=ci-1), copy[ci][..][x] = off[x+dx]
                    const int w = cc & 127;
                    const __half h0 = __float2half(v0), h1 = __float2half(v1);
                    const size_t rowoff = (size_t)r * HWSZ + (size_t)(cc & ~127);
                    __half* c0 = g_offh3 + ((size_t)0 * BATCH + bz) * CC * HWSZ + rowoff;  // dx=-1: x=w+1
                    __half* c1 = g_offh3 + ((size_t)1 * BATCH + bz) * CC * HWSZ + rowoff;  // dx= 0: x=w
                    __half* c2 = g_offh3 + ((size_t)2 * BATCH + bz) * CC * HWSZ + rowoff;  // dx=+1: x=w-1
                    *(__half2*)&c1[w] = __halves2half2(h0, h1);
                    c0[w + 1] = h0;
                    if (w + 2 < 128) c0[w + 2] = h1;
                    if (w > 0) c2[w - 1] = h0;
                    c2[w] = h1;
                }
            }
        }
    }
}

// ---------------- fused im2col + fp16 GEMM for the 3x3 offset/mask conv ----------------
// B rows loaded contiguously from the pre-shifted copies g_offh3; k-pairs merged to words.
__global__ __launch_bounds__(256, 2) void hgemm_om(
    const float* __restrict__ bias, float* __restrict__ C)
{
    const int bz = blockIdx.z;
    const __half* A = g_omwh;
    float* Cb = C + (size_t)bz * OMCH * HWSZ;

    __shared__ __align__(16) __half As[2][128 * AHSTR];
    __shared__ __align__(16) unsigned int Bs[2][16 * BWSTR];

    const int tid = threadIdx.x, lane = tid & 31, warp = tid >> 5;
    const int gid = lane >> 2, tig = lane & 3;
    const int wm = (warp >> 2) * 64, wn = (warp & 3) * 32;
    const int bm = blockIdx.y * 128;
    const int h = blockIdx.x;          // image row == n-tile
    const int bn = h * 128;

    const int arow = tid >> 1, ac = (tid & 1) * 16;
    const __half* Ap = A + (size_t)(bm + arow) * KBIG + ac;
    const int apred = ((bm + arow) < OMCH) ? 16 : 0;

    // B loader: kp = tid>>4 (0..15), chunk = tid&15 (8 halves each)
    const int kp = tid >> 4;
    const int chunk = tid & 15;

    float acc[4][4][4];
    #pragma unroll
    for (int mi = 0; mi < 4; mi++)
        #pragma unroll
        for (int ni = 0; ni < 4; ni++)
            #pragma unroll
            for (int q = 0; q < 4; q++) acc[mi][ni][q] = 0.f;

    const int nk = KBIG / 32;   // 36
    uint4 bva, bvb;

    auto load_a = [&](int kb, int buf) {
        unsigned int sa = (unsigned int)__cvta_generic_to_shared(&As[buf][arow * AHSTR + ac]);
        const __half* ga = Ap + kb * 32;
        asm volatile("cp.async.ca.shared.global [%0], [%1], 16, %2;\n" :: "r"(sa), "l"(ga), "r"(apred));
        asm volatile("cp.async.ca.shared.global [%0], [%1], 16, %2;\n" :: "r"(sa + 16), "l"(ga + 8), "r"(apred));
        asm volatile("cp.async.commit_group;\n");
    };
    auto load_b_regs = [&](int kb) {
        #pragma unroll
        for (int rr = 0; rr < 2; rr++) {
            int ck = kb * 32 + 2 * kp + rr;
            int c  = ck / 9;
            int kk = ck - 9 * c;
            int dy = kk / 3 - 1;
            int ci = kk - (kk / 3) * 3;     // dx + 1
            int hs = h + dy;
            uint4 v = make_uint4(0u, 0u, 0u, 0u);
            if ((unsigned)hs < 128u) {
                const __half* src = g_offh3 + (((size_t)ci * BATCH + bz) * CC + c) * HWSZ
                                  + hs * 128 + chunk * 8;
                v = *(const uint4*)src;
            }
            if (rr == 0) bva = v; else bvb = v;
        }
    };
    auto sts_b = [&](int buf) {
        unsigned int* dst = &Bs[buf][kp * BWSTR + chunk * 8];
        uint4 o1, o2;
        o1.x = __byte_perm(bva.x, bvb.x, 0x5410);
        o1.y = __byte_perm(bva.x, bvb.x, 0x7632);
        o1.z = __byte_perm(bva.y, bvb.y, 0x5410);
        o1.w = __byte_perm(bva.y, bvb.y, 0x7632);
        o2.x = __byte_perm(bva.z, bvb.z, 0x5410);
        o2.y = __byte_perm(bva.z, bvb.z, 0x7632);
        o2.z = __byte_perm(bva.w, bvb.w, 0x5410);
        o2.w = __byte_perm(bva.w, bvb.w, 0x7632);
        *(uint4*)dst = o1;
        *(uint4*)(dst + 4) = o2;
    };

    load_a(0, 0);
    load_b_regs(0);
    asm volatile("cp.async.wait_group 0;\n");
    sts_b(0);
    __syncthreads();

    for (int kb = 0; kb < nk; kb++) {
        const int cur = kb & 1;
        if (kb + 1 < nk) {
            load_a(kb + 1, cur ^ 1);
            load_b_regs(kb + 1);
        }
        HGEMM_CORE();
        if (kb + 1 < nk) {
            asm volatile("cp.async.wait_group 0;\n");
            __syncthreads();
            sts_b(cur ^ 1);
        }
        __syncthreads();
    }

    #pragma unroll
    for (int mi = 0; mi < 4; mi++) {
        const int r0 = bm + wm + mi * 16 + gid;
        const int r1 = r0 + 8;
        const bool ok0 = r0 < OMCH, ok1 = r1 < OMCH;
        const float bv0 = ok0 ? bias[r0] : 0.f;
        const float bv1 = ok1 ? bias[r1] : 0.f;
        #pragma unroll
        for (int ni = 0; ni < 4; ni++) {
            const int cc = bn + wn + ni * 8 + 2 * tig;
            if (ok0) {
                size_t o = (size_t)r0 * HWSZ + cc;
                *(float2*)&Cb[o] = make_float2(acc[mi][ni][0] + bv0, acc[mi][ni][1] + bv0);
            }
            if (ok1) {
                size_t o = (size_t)r1 * HWSZ + cc;
                *(float2*)&Cb[o] = make_float2(acc[mi][ni][2] + bv1, acc[mi][ni][3] + bv1);
            }
        }
    }
}

// ---------------- launch ----------------
extern "C" void kernel_launch(void* const* d_in, const int* in_sizes, int n_in,
                              void* d_out, int out_size) {
    const float* feat_l  = (const float*)d_in[0];
    const float* feat_s  = (const float*)d_in[1];
    const float* atten_w = (const float*)d_in[2];
    const float* atten_b = (const float*)d_in[3];
    const float* bn_g    = (const float*)d_in[4];
    const float* bn_b    = (const float*)d_in[5];
    const float* bn_m    = (const float*)d_in[6];
    const float* bn_v    = (const float*)d_in[7];
    const float* fsm_w   = (const float*)d_in[8];
    const float* fsm_b   = (const float*)d_in[9];
    const float* om_b    = (const float*)d_in[12];
    const float* dcn_b   = (const float*)d_in[14];
    float* out = (float*)d_out;

    float *p_cat, *p_om;
    __half *p_armWh, *p_offwh, *p_dcnwh, *p_flh, *p_cath, *p_Sh;
    cudaGetSymbolAddress((void**)&p_cat,   g_cat);
    cudaGetSymbolAddress((void**)&p_om,    g_om);
    cudaGetSymbolAddress((void**)&p_armWh, g_armWh);
    cudaGetSymbolAddress((void**)&p_offwh, g_offwh);
    cudaGetSymbolAddress((void**)&p_dcnwh, g_dcnwh);
    cudaGetSymbolAddress((void**)&p_flh,   g_flh);
    cudaGetSymbolAddress((void**)&p_cath,  g_cath);
    cudaGetSymbolAddress((void**)&p_Sh,    g_Sh);

    // 1) SE gate + weight packing (+ offh3 edge zeroing) + prep
    pool_kernel<<<BATCH * CC, 256>>>(feat_l);
    atten_kernel<<<1, 256>>>(atten_w, atten_b, bn_g, bn_b, bn_m, bn_v);
    armw_kernel<<<128, 256>>>(fsm_w);
    whpack_kernel<<<(OMCH * KBIG + 255) / 256, 256>>>(
        (const float*)d_in[11], (const float*)d_in[13], (const float*)d_in[10]);
    prep_kernel<<<(BATCH * CC * HWSZ + 255) / 256, 256>>>(feat_l, feat_s);

    // 2) feat_arm = armW @ feat_l + fsm_b -> fp32 g_cat + fp16 g_cath
    hgemm<3><<<dim3(HWSZ / 128, 1, BATCH), 256>>>(
        p_armWh, CC, (size_t)CC * CC,
        (const unsigned int*)p_flh, (size_t)(CC / 2) * HWSZ,
        fsm_b,
        p_cat, (size_t)2 * CC * HWSZ,
        p_cath, (size_t)2 * CC * HWSZ,
        nullptr, 0,
        CC, CC, HWSZ);

    // 3) off_feat = off_w @ [feat_arm; feat_up] -> 3 shifted fp16 copies g_offh3
    hgemm<6><<<dim3(HWSZ / 128, 1, BATCH), 256>>>(
        p_offwh, 2 * CC, 0,
        (const unsigned int*)p_cath, (size_t)CC * HWSZ,
        nullptr,
        nullptr, 0,
        nullptr, 0,
        nullptr, 0,
        CC, 2 * CC, HWSZ);

    // 4) fused im2col + 3x3 conv (M=216, K=1152) -> fp32 g_om
    hgemm_om<<<dim3(128, 2, BATCH), 256>>>(om_b, p_om);

    // 5) bilinear sample + mask -> fp16 interleaved g_Sh
    sample_kernel<<<(BATCH * DGRP * KPTS * HWSZ + 255) / 256, 256>>>();

    // 6) DCN GEMM + relu + bias + feat_arm -> out
    hgemm<2><<<dim3(HWSZ / 128, 1, BATCH), 256>>>(
        p_dcnwh, KBIG, 0,
        (const unsigned int*)p_Sh, (size_t)(KBIG / 2) * HWSZ,
        dcn_b,
        out, (size_t)CC * HWSZ,
        nullptr, 0,
        p_cat, (size_t)2 * CC * HWSZ,
        CC, KBIG, HWSZ);
}